// round 1
// baseline (speedup 1.0000x reference)
#include <cuda_runtime.h>
#include <math.h>

#define B_ 32
#define L_ 512
#define D_ 768
#define C_ 97

// ---------------- scratch (device globals; no allocations allowed) ----------------
__device__ float g_x[B_*L_*D_];        // evolving x (50.3 MB)
__device__ float g_p[B_*C_*D_];        // evolving p (9.5 MB)
__device__ float g_p0[C_*D_];
__device__ float g_H[B_*C_*D_];        // tanh(p@W1 + t1)
__device__ float g_gpart[24*128*768];  // split-K partials for small-M GEMMs
__device__ float g_bpart[3*4*B_*D_];   // pass-B partials (u2, e1, e2)
__device__ float g_kv[2*D_];           // kw@sw2 per RA
__device__ float g_gv[2*D_];           // gw1+gw2 per RA
__device__ float g_sk1[B_*C_];
__device__ float g_sk2[B_*L_];
__device__ float g_a2[B_*L_];
__device__ float g_u[B_*D_];
__device__ float g_ctx[B_*D_];
__device__ float g_gc[B_];
__device__ float g_possum[2*B_];
__device__ float g_e12[B_*2*D_];       // [e1 | e2] per batch row (32 x 1536)
__device__ float g_t1[B_*D_];
__device__ float g_logits[B_*C_];

__device__ __forceinline__ float warpsum(float v){
#pragma unroll
    for (int o = 16; o > 0; o >>= 1) v += __shfl_xor_sync(0xffffffffu, v, o);
    return v;
}
__device__ __forceinline__ float warpmax(float v){
#pragma unroll
    for (int o = 16; o > 0; o >>= 1) v = fmaxf(v, __shfl_xor_sync(0xffffffffu, v, o));
    return v;
}
__device__ __forceinline__ float sigm(float z){ return 1.f/(1.f + expf(-z)); }

// ---------------- per-layer prep: kv = kw@sw2 (row dots), gv = gw1+gw2 ----------------
__global__ void k_prep(const float* __restrict__ kw, const float* __restrict__ sw,
                       const float* __restrict__ gw, int li){
    int gtid = blockIdx.x*blockDim.x + threadIdx.x;
    if (gtid < 2*D_){
        int ra = gtid/D_, dd = gtid%D_;
        const float* g = gw + (li*2+ra)*2*D_;
        g_gv[ra*D_+dd] = g[dd] + g[D_+dd];
    }
    int wid = gtid >> 5, lane = gtid & 31;
    if (wid < 2*D_){
        int ra = wid/D_, d = wid%D_;
        const float* krow = kw + ((size_t)(li*2+ra)*D_ + d)*D_;
        const float* s2   = sw + (li*2+ra)*2*D_ + D_;
        float acc = 0.f;
        for (int e = lane; e < D_; e += 32) acc += krow[e]*s2[e];
        acc = warpsum(acc);
        if (!lane) g_kv[ra*D_+d] = acc;
    }
}

// ---------------- sk1[b,c] = p_row . kv[0] (warp per row) ----------------
__global__ void k_sk1(){
    int w = (blockIdx.x*blockDim.x + threadIdx.x) >> 5;
    int lane = threadIdx.x & 31;
    if (w >= B_*C_) return;
    const float* pr = g_p + (size_t)w*D_;
    float acc = 0.f;
    for (int e = lane; e < D_; e += 32) acc += pr[e]*g_kv[e];
    acc = warpsum(acc);
    if (!lane) g_sk1[w] = acc;
}

// ---------------- softmax over C + u1[b,:] = sum_c a_c p[b,c,:] ----------------
__global__ void k_pattn1(){
    __shared__ float a[C_];
    int b = blockIdx.x, tid = threadIdx.x;
    if (tid < C_) a[tid] = g_sk1[b*C_+tid];
    __syncthreads();
    if (tid == 0){
        float m = -1e30f;
        for (int c = 0; c < C_; c++) m = fmaxf(m, a[c]);
        float s = 0.f;
        for (int c = 0; c < C_; c++){ a[c] = expf(a[c]-m); s += a[c]; }
        float inv = 1.f/s;
        for (int c = 0; c < C_; c++) a[c] *= inv;
    }
    __syncthreads();
    for (int d = tid; d < D_; d += blockDim.x){
        const float* pb = g_p + (size_t)b*C_*D_ + d;
        float acc = 0.f;
        for (int c = 0; c < C_; c++) acc += a[c]*pb[(size_t)c*D_];
        g_u[b*D_+d] = acc;
    }
}

// ---------------- small-M split-K GEMM: out[M,N] = A[M,K] @ W[K,N] (+bias) ----------------
__global__ void k_smgemm_part(const float* __restrict__ A, const float* __restrict__ W,
                              int M, int K, int N){
    __shared__ float As[32*64];
    int n  = blockIdx.x*64 + threadIdx.x;
    int kc = blockIdx.y;
    int m0 = blockIdx.z*32;
    for (int i = threadIdx.x; i < 32*64; i += 64){
        int mm = i >> 6, kk = i & 63;
        int m = m0 + mm;
        As[i] = (m < M) ? A[(size_t)m*K + kc*64 + kk] : 0.f;
    }
    __syncthreads();
    float acc[32];
#pragma unroll
    for (int i = 0; i < 32; i++) acc[i] = 0.f;
    const float* Wp = W + (size_t)(kc*64)*N + n;
#pragma unroll 4
    for (int kk = 0; kk < 64; kk++){
        float w = Wp[(size_t)kk*N];
#pragma unroll
        for (int mm = 0; mm < 32; mm++) acc[mm] += As[mm*64+kk]*w;
    }
    float* outp = g_gpart + ((size_t)kc*128 + m0)*768 + n;
#pragma unroll
    for (int mm = 0; mm < 32; mm++) outp[(size_t)mm*768] = acc[mm];
}
__global__ void k_smgemm_red(float* __restrict__ out, const float* __restrict__ bias,
                             int M, int N, int kch){
    int idx = blockIdx.x*blockDim.x + threadIdx.x;
    if (idx >= M*N) return;
    int m = idx / N, n = idx - m*N;
    float s = bias ? bias[n] : 0.f;
    for (int kc = 0; kc < kch; kc++) s += g_gpart[((size_t)kc*128 + m)*768 + n];
    out[idx] = s;
}

__global__ void k_bcast_p(){
    int idx = blockIdx.x*blockDim.x + threadIdx.x;
    if (idx >= B_*C_*D_) return;
    g_p[idx] = g_p0[idx % (C_*D_)];
}

// ---------------- gc[b] = ctx[b] . gw1 + gb ----------------
__global__ void k_gcdot(const float* __restrict__ gvec, const float* __restrict__ gbp){
    int b = blockIdx.x, tid = threadIdx.x;
    float acc = 0.f;
    for (int e = tid; e < D_; e += 256) acc += g_ctx[b*D_+e]*gvec[e];
    __shared__ float sm[8];
    acc = warpsum(acc);
    if ((tid & 31) == 0) sm[tid>>5] = acc;
    __syncthreads();
    if (tid == 0){
        float s = 0.f;
        for (int i = 0; i < 8; i++) s += sm[i];
        g_gc[b] = s + gbp[0];
    }
}

// ---------------- pass A over x rows: gate, x_new = 2x + g*ctx, sk2 dot, mask ----------------
__global__ void k_passA(const float* __restrict__ xsrc, const int* __restrict__ mask){
    int w = (blockIdx.x*blockDim.x + threadIdx.x) >> 5;
    int lane = threadIdx.x & 31;
    if (w >= B_*L_) return;
    int b = w >> 9;  // /512
    const float* xr = xsrc + (size_t)w*D_;
    float xv[24];
    float d1 = 0.f;
#pragma unroll
    for (int j = 0; j < 24; j++){
        int e = lane + j*32;
        xv[j] = xr[e];
        d1 += xv[j]*g_gv[e];
    }
    d1 = warpsum(d1);
    float g = sigm(d1 + g_gc[b]);
    float* xo = g_x + (size_t)w*D_;
    const float* ctx = g_ctx + b*D_;
    float d2 = 0.f;
#pragma unroll
    for (int j = 0; j < 24; j++){
        int e = lane + j*32;
        float xn = 2.f*xv[j] + g*ctx[e];
        xo[e] = xn;
        d2 += xn * g_kv[D_+e];
    }
    d2 = warpsum(d2);
    if (!lane) g_sk2[w] = mask[w] ? d2 : -1e30f;
}

// ---------------- masked softmax over L (512 threads per batch row) ----------------
__global__ void k_softmax2(){
    int b = blockIdx.x, tid = threadIdx.x;  // 512 threads
    __shared__ float sm[16];
    __shared__ float bc;
    float v = g_sk2[b*L_+tid];
    float m = warpmax(v);
    if ((tid & 31) == 0) sm[tid>>5] = m;
    __syncthreads();
    if (tid == 0){
        float mm = sm[0];
        for (int i = 1; i < 16; i++) mm = fmaxf(mm, sm[i]);
        bc = mm;
    }
    __syncthreads();
    float e = expf(v - bc);
    float s = warpsum(e);
    __syncthreads();
    if ((tid & 31) == 0) sm[tid>>5] = s;
    __syncthreads();
    if (tid == 0){
        float ss = 0.f;
        for (int i = 0; i < 16; i++) ss += sm[i];
        bc = ss;
    }
    __syncthreads();
    g_a2[b*L_+tid] = e / bc;
}

__global__ void k_possum(const float* __restrict__ pos1, const float* __restrict__ pos2){
    int b = blockIdx.x, tid = threadIdx.x;  // 512
    __shared__ float sm1[16], sm2[16];
    float v1 = pos1[b*L_+tid], v2 = pos2[b*L_+tid];
    v1 = warpsum(v1); v2 = warpsum(v2);
    if ((tid & 31) == 0){ sm1[tid>>5] = v1; sm2[tid>>5] = v2; }
    __syncthreads();
    if (tid == 0){
        float s1 = 0.f, s2 = 0.f;
        for (int i = 0; i < 16; i++){ s1 += sm1[i]; s2 += sm2[i]; }
        g_possum[b] = s1; g_possum[B_+b] = s2;
    }
}

// ---------------- pass B: u2 = a2 @ x (and pooled e1/e2 on last layer) ----------------
__global__ void k_passB_part(const float* __restrict__ pos1, const float* __restrict__ pos2, int pool){
    int blk = blockIdx.x; int b = blk >> 2, ch = blk & 3;
    int t = threadIdx.x;  // 768
    __shared__ float sa[128], s1[128], s2[128];
    if (t < 128){
        int l = ch*128 + t;
        sa[t] = g_a2[b*L_+l];
        if (pool){ s1[t] = pos1[b*L_+l]; s2[t] = pos2[b*L_+l]; }
    }
    __syncthreads();
    const float* xb = g_x + ((size_t)b*L_ + ch*128)*D_ + t;
    float au = 0.f, ae1 = 0.f, ae2 = 0.f;
    for (int l = 0; l < 128; l++){
        float xv = xb[(size_t)l*D_];
        au += sa[l]*xv;
        if (pool){ ae1 += s1[l]*xv; ae2 += s2[l]*xv; }
    }
    g_bpart[((0*4+ch)*B_ + b)*D_ + t] = au;
    if (pool){
        g_bpart[((1*4+ch)*B_ + b)*D_ + t] = ae1;
        g_bpart[((2*4+ch)*B_ + b)*D_ + t] = ae2;
    }
}
__global__ void k_passB_red(int pool){
    int idx = blockIdx.x*blockDim.x + threadIdx.x;
    if (idx >= B_*D_) return;
    int b = idx / D_, t = idx - b*D_;
    float u = 0.f, e1 = 0.f, e2 = 0.f;
    for (int ch = 0; ch < 4; ch++){
        u += g_bpart[((0*4+ch)*B_ + b)*D_ + t];
        if (pool){
            e1 += g_bpart[((1*4+ch)*B_ + b)*D_ + t];
            e2 += g_bpart[((2*4+ch)*B_ + b)*D_ + t];
        }
    }
    g_u[idx] = u;
    if (pool){
        g_e12[b*2*D_ + t]      = e1 / g_possum[b];
        g_e12[b*2*D_ + D_ + t] = e2 / g_possum[B_+b];
    }
}

// ---------------- p update: p = 2p + sigmoid(p.gv2 + gc2) * ctx2 ----------------
__global__ void k_pupd(){
    int w = (blockIdx.x*blockDim.x + threadIdx.x) >> 5;
    int lane = threadIdx.x & 31;
    if (w >= B_*C_) return;
    int b = w / C_;
    float* pr = g_p + (size_t)w*D_;
    float pv[24];
    float d1 = 0.f;
#pragma unroll
    for (int j = 0; j < 24; j++){
        int e = lane + j*32;
        pv[j] = pr[e];
        d1 += pv[j]*g_gv[D_+e];
    }
    d1 = warpsum(d1);
    float g = sigm(d1 + g_gc[b]);
    const float* ctx = g_ctx + b*D_;
#pragma unroll
    for (int j = 0; j < 24; j++){
        int e = lane + j*32;
        pr[e] = 2.f*pv[j] + g*ctx[e];
    }
}

// ---------------- big SGEMM: H = tanh(p[3104,768] @ W1[768,768] + t1[b]) ----------------
__global__ void __launch_bounds__(256) k_sgemm_H(const float* __restrict__ W){
    __shared__ float As[8][128];
    __shared__ float Bs[8][128];
    const int M = B_*C_, N = 768, K = 768;
    int m0 = blockIdx.y*128, n0 = blockIdx.x*128;
    int tid = threadIdx.x;
    int tr = tid >> 4, tc = tid & 15;
    float acc[8][8];
#pragma unroll
    for (int i = 0; i < 8; i++)
#pragma unroll
        for (int j = 0; j < 8; j++) acc[i][j] = 0.f;
    int aM = tid >> 1, aK = (tid & 1)*4;
    int bK = tid >> 5, bN = (tid & 31)*4;
    for (int k0 = 0; k0 < K; k0 += 8){
        float4 av;
        if (m0 + aM < M) av = *(const float4*)(g_p + (size_t)(m0+aM)*K + k0 + aK);
        else av = make_float4(0.f,0.f,0.f,0.f);
        As[aK+0][aM] = av.x; As[aK+1][aM] = av.y; As[aK+2][aM] = av.z; As[aK+3][aM] = av.w;
        *(float4*)&Bs[bK][bN] = *(const float4*)(W + (size_t)(k0+bK)*N + n0 + bN);
        __syncthreads();
#pragma unroll
        for (int k = 0; k < 8; k++){
            float ra[8], rb[8];
            *(float4*)ra     = *(float4*)&As[k][tr*8];
            *(float4*)(ra+4) = *(float4*)&As[k][tr*8+4];
            *(float4*)rb     = *(float4*)&Bs[k][tc*8];
            *(float4*)(rb+4) = *(float4*)&Bs[k][tc*8+4];
#pragma unroll
            for (int i = 0; i < 8; i++)
#pragma unroll
                for (int j = 0; j < 8; j++) acc[i][j] += ra[i]*rb[j];
        }
        __syncthreads();
    }
#pragma unroll
    for (int i = 0; i < 8; i++){
        int m = m0 + tr*8 + i;
        if (m >= M) continue;
        int b = m / C_;
        const float* t1 = g_t1 + b*D_;
#pragma unroll
        for (int j = 0; j < 8; j++){
            int n = n0 + tc*8 + j;
            g_H[(size_t)m*N + n] = tanhf(acc[i][j] + t1[n]);
        }
    }
}

// ---------------- logits + argmax ----------------
__global__ void k_logits(const float* __restrict__ fc2w, const float* __restrict__ fc2b,
                         float* __restrict__ out){
    int w = (blockIdx.x*blockDim.x + threadIdx.x) >> 5;
    int lane = threadIdx.x & 31;
    if (w >= B_*C_) return;
    const float* h = g_H + (size_t)w*D_;
    float acc = 0.f;
    for (int e = lane; e < D_; e += 32) acc += h[e]*fc2w[e];
    acc = warpsum(acc);
    if (!lane){
        float lg = sigm(acc + fc2b[0]);
        g_logits[w] = lg;
        if (out) out[w] = lg;
    }
}
__global__ void k_argmax(float* __restrict__ out){
    int b = blockIdx.x;
    if (threadIdx.x == 0){
        float best = g_logits[b*C_]; int bi = 0;
        for (int c = 1; c < C_; c++){
            float v = g_logits[b*C_+c];
            if (v > best){ best = v; bi = c; }
        }
        out[b] = (float)bi;
    }
}

// ---------------- host orchestration ----------------
extern "C" void kernel_launch(void* const* d_in, const int* in_sizes, int n_in,
                              void* d_out, int out_size){
    (void)in_sizes; (void)n_in;
    const float* x_in  = (const float*)d_in[0];
    const float* pos1  = (const float*)d_in[1];
    const float* pos2  = (const float*)d_in[2];
    const int*   mask  = (const int*)  d_in[3];
    const float* emb   = (const float*)d_in[4];
    const float* rel_w = (const float*)d_in[5];
    const float* rel_b = (const float*)d_in[6];
    // d_in[7] qw, d_in[8] qb: provably unused (softmax separability)
    const float* kw    = (const float*)d_in[9];
    // d_in[10] kb: constant, cancels in softmax
    const float* vw    = (const float*)d_in[11];
    const float* vb    = (const float*)d_in[12];
    const float* sw    = (const float*)d_in[13];
    // d_in[14] sb: constant, cancels in softmax
    const float* gw    = (const float*)d_in[15];
    const float* gb    = (const float*)d_in[16];
    const float* fc1w  = (const float*)d_in[17];
    const float* fc1b  = (const float*)d_in[18];
    const float* fc2w  = (const float*)d_in[19];
    const float* fc2b  = (const float*)d_in[20];
    float* out = (float*)d_out;

    float *p_p0, *p_x, *p_u, *p_ctx, *p_e12, *p_t1;
    cudaGetSymbolAddress((void**)&p_p0,  g_p0);
    cudaGetSymbolAddress((void**)&p_x,   g_x);
    cudaGetSymbolAddress((void**)&p_u,   g_u);
    cudaGetSymbolAddress((void**)&p_ctx, g_ctx);
    cudaGetSymbolAddress((void**)&p_e12, g_e12);
    cudaGetSymbolAddress((void**)&p_t1,  g_t1);

    // p0 = emb @ rel_w + rel_b ; broadcast to (B,C,D)
    k_smgemm_part<<<dim3(12,12,4),64>>>(emb, rel_w, C_, 768, 768);
    k_smgemm_red<<<(C_*768+255)/256,256>>>(p_p0, rel_b, C_, 768, 12);
    k_bcast_p<<<(B_*C_*D_+255)/256,256>>>();
    k_possum<<<B_,512>>>(pos1, pos2);

    for (int li = 0; li < 2; li++){
        k_prep<<<192,256>>>(kw, sw, gw, li);
        // --- RA1 (queries=x, kv=p) ---
        k_sk1<<<(B_*C_+7)/8,256>>>();
        k_pattn1<<<B_,256>>>();
        k_smgemm_part<<<dim3(12,12,1),64>>>(p_u, vw + (size_t)(li*2+0)*D_*D_, B_, 768, 768);
        k_smgemm_red<<<(B_*768+255)/256,256>>>(p_ctx, vb + (li*2+0)*D_, B_, 768, 12);
        k_gcdot<<<B_,256>>>(gw + (li*2+0)*2*D_, gb + (li*2+0));
        k_passA<<<(B_*L_+7)/8,256>>>(li == 0 ? x_in : (const float*)p_x, mask);
        // --- RA2 (queries=p, kv=x_new, masked) ---
        k_softmax2<<<B_,512>>>();
        k_passB_part<<<B_*4,768>>>(pos1, pos2, li == 1);
        k_passB_red<<<(B_*D_+255)/256,256>>>(li == 1);
        k_smgemm_part<<<dim3(12,12,1),64>>>(p_u, vw + (size_t)(li*2+1)*D_*D_, B_, 768, 768);
        k_smgemm_red<<<(B_*768+255)/256,256>>>(p_ctx, vb + (li*2+1)*D_, B_, 768, 12);
        k_gcdot<<<B_,256>>>(gw + (li*2+1)*2*D_, gb + (li*2+1));
        k_pupd<<<(B_*C_+7)/8,256>>>();
    }

    // t1 = [e1|e2] @ fc1_w[768:2304] + fc1_b
    k_smgemm_part<<<dim3(12,24,1),64>>>(p_e12, fc1w + (size_t)768*768, B_, 1536, 768);
    k_smgemm_red<<<(B_*768+255)/256,256>>>(p_t1, fc1b, B_, 768, 24);
    // H = tanh(p @ fc1_w[0:768] + t1)
    k_sgemm_H<<<dim3(6,25),256>>>(fc1w);
    // logits + pred
    bool wlog = out_size >= B_*C_;
    k_logits<<<(B_*C_+7)/8,256>>>(fc2w, fc2b, wlog ? out : nullptr);
    if (out_size >= B_*C_ + B_)      k_argmax<<<B_,32>>>(out + B_*C_);
    else if (out_size == B_)         k_argmax<<<B_,32>>>(out);
}

// round 2
// speedup vs baseline: 1.1329x; 1.1329x over previous
#include <cuda_runtime.h>
#include <math.h>

#define B_ 32
#define L_ 512
#define D_ 768
#define C_ 97
#define GM (B_*C_)   // 3104

// ---------------- scratch ----------------
__device__ float g_x[B_*L_*D_];
__device__ float g_p[B_*C_*D_];
__device__ float g_p0[C_*D_];
__device__ float g_gpart[24*128*768];
__device__ float g_bpart[12*B_*D_];    // [grp(0=u,1=e1,2=e2)*4+ch][B][D]
__device__ float g_kv[2*D_];
__device__ float g_gv[2*D_];
__device__ float g_sk2[B_*L_];
__device__ float g_a2[B_*L_];
__device__ float g_u[B_*D_];
__device__ float g_ctx[B_*D_];
__device__ float g_gc[B_];
__device__ float g_possum[2*B_];
__device__ float g_t1[B_*D_];
__device__ float g_lacc[GM];

__device__ __forceinline__ float warpsum(float v){
#pragma unroll
    for (int o = 16; o > 0; o >>= 1) v += __shfl_xor_sync(0xffffffffu, v, o);
    return v;
}
__device__ __forceinline__ float warpmax(float v){
#pragma unroll
    for (int o = 16; o > 0; o >>= 1) v = fmaxf(v, __shfl_xor_sync(0xffffffffu, v, o));
    return v;
}
__device__ __forceinline__ float sigm(float z){ return 1.f/(1.f + expf(-z)); }
__device__ __forceinline__ unsigned f2tf(float f){
    unsigned u; asm("cvt.rna.tf32.f32 %0, %1;" : "=r"(u) : "f"(f)); return u;
}
__device__ __forceinline__ void mma_tf32(float c[4], unsigned a0, unsigned a1,
                                         unsigned a2, unsigned a3,
                                         unsigned b0, unsigned b1){
    asm volatile("mma.sync.aligned.m16n8k8.row.col.f32.tf32.tf32.f32 "
        "{%0,%1,%2,%3}, {%4,%5,%6,%7}, {%8,%9}, {%0,%1,%2,%3};\n"
        : "+f"(c[0]), "+f"(c[1]), "+f"(c[2]), "+f"(c[3])
        : "r"(a0), "r"(a1), "r"(a2), "r"(a3), "r"(b0), "r"(b1));
}

// ---------------- prep: kv = kw@sw2, gv = gw1+gw2, zero gc ----------------
__global__ void k_prep(const float* __restrict__ kw, const float* __restrict__ sw,
                       const float* __restrict__ gw, int li){
    int gtid = blockIdx.x*blockDim.x + threadIdx.x;
    if (gtid < B_) g_gc[gtid] = 0.f;
    if (gtid < 2*D_){
        int ra = gtid/D_, dd = gtid%D_;
        const float* g = gw + (li*2+ra)*2*D_;
        g_gv[ra*D_+dd] = g[dd] + g[D_+dd];
    }
    int wid = gtid >> 5, lane = gtid & 31;
    if (wid < 2*D_){
        int ra = wid/D_, d = wid%D_;
        const float* krow = kw + ((size_t)(li*2+ra)*D_ + d)*D_;
        const float* s2   = sw + (li*2+ra)*2*D_ + D_;
        float acc = 0.f;
        for (int e = lane; e < D_; e += 32) acc += krow[e]*s2[e];
        acc = warpsum(acc);
        if (!lane) g_kv[ra*D_+d] = acc;
    }
}

// ---------------- RA1 fused: scores over C, softmax, u = a@p ----------------
__global__ void k_ra1(){
    __shared__ float a[C_];
    int b = blockIdx.x, tid = threadIdx.x;  // 256
    int w = tid >> 5, lane = tid & 31;
    for (int c = w; c < C_; c += 8){
        const float* pr = g_p + ((size_t)b*C_ + c)*D_;
        float acc = 0.f;
        for (int e = lane; e < D_; e += 32) acc += pr[e]*g_kv[e];
        acc = warpsum(acc);
        if (!lane) a[c] = acc;
    }
    __syncthreads();
    if (tid == 0){
        float m = -1e30f;
        for (int c = 0; c < C_; c++) m = fmaxf(m, a[c]);
        float s = 0.f;
        for (int c = 0; c < C_; c++){ a[c] = expf(a[c]-m); s += a[c]; }
        float inv = 1.f/s;
        for (int c = 0; c < C_; c++) a[c] *= inv;
    }
    __syncthreads();
    for (int d = tid; d < D_; d += 256){
        const float* pb = g_p + (size_t)b*C_*D_ + d;
        float acc = 0.f;
        for (int c = 0; c < C_; c++) acc += a[c]*pb[(size_t)c*D_];
        g_u[b*D_+d] = acc;
    }
}

// ---------------- small-M split-K GEMM part ----------------
// amode 0: A plain [M,K]; 1: A = sum4(bpart grp0); 2: A = [e1|e2] from bpart
__global__ void k_smgemm_part(const float* __restrict__ A, int M, int K,
                              const float* __restrict__ W, int amode){
    __shared__ float As[32*64];
    int n  = blockIdx.x*64 + threadIdx.x;
    int kc = blockIdx.y;
    int m0 = blockIdx.z*32;
    for (int i = threadIdx.x; i < 32*64; i += 64){
        int mm = i >> 6, kk = i & 63;
        int m = m0 + mm, kg = kc*64 + kk;
        float v = 0.f;
        if (m < M){
            if (amode == 0) v = A[(size_t)m*K + kg];
            else if (amode == 1){
                v = g_bpart[(0*B_+m)*D_+kg] + g_bpart[(1*B_+m)*D_+kg]
                  + g_bpart[(2*B_+m)*D_+kg] + g_bpart[(3*B_+m)*D_+kg];
            } else {
                if (kg < 768){
                    float s = g_bpart[((4+0)*B_+m)*D_+kg] + g_bpart[((4+1)*B_+m)*D_+kg]
                            + g_bpart[((4+2)*B_+m)*D_+kg] + g_bpart[((4+3)*B_+m)*D_+kg];
                    v = s / g_possum[m];
                } else {
                    int kg2 = kg - 768;
                    float s = g_bpart[((8+0)*B_+m)*D_+kg2] + g_bpart[((8+1)*B_+m)*D_+kg2]
                            + g_bpart[((8+2)*B_+m)*D_+kg2] + g_bpart[((8+3)*B_+m)*D_+kg2];
                    v = s / g_possum[B_+m];
                }
            }
        }
        As[i] = v;
    }
    __syncthreads();
    float acc[32];
#pragma unroll
    for (int i = 0; i < 32; i++) acc[i] = 0.f;
    const float* Wp = W + (size_t)(kc*64)*768 + n;
#pragma unroll 4
    for (int kk = 0; kk < 64; kk++){
        float w = Wp[(size_t)kk*768];
#pragma unroll
        for (int mm = 0; mm < 32; mm++) acc[mm] += As[mm*64+kk]*w;
    }
    float* outp = g_gpart + ((size_t)kc*128 + m0)*768 + n;
#pragma unroll
    for (int mm = 0; mm < 32; mm++) outp[(size_t)mm*768] = acc[mm];
}

// ---------------- split-K reduce (+bias, + optional gc dot) ----------------
__global__ void k_smgemm_red(float* __restrict__ out, const float* __restrict__ bias,
                             int M, int kch, const float* __restrict__ gvec,
                             const float* __restrict__ gbp){
    int idx = blockIdx.x*blockDim.x + threadIdx.x;
    if (idx >= M*768) return;
    int m = idx / 768, n = idx - m*768;
    float s = bias ? bias[n] : 0.f;
    for (int kc = 0; kc < kch; kc++) s += g_gpart[((size_t)kc*128 + m)*768 + n];
    out[idx] = s;
    if (gvec){
        float p = s * gvec[n];
        p = warpsum(p);
        if ((threadIdx.x & 31) == 0)
            atomicAdd(&g_gc[m], p + ((n == 0) ? gbp[0] : 0.f));
    }
}

__global__ void k_bcast_p(){
    int idx = blockIdx.x*blockDim.x + threadIdx.x;
    const int Q = C_*D_/4;
    if (idx >= B_*Q) return;
    ((float4*)g_p)[idx] = ((const float4*)g_p0)[idx % Q];
}

// ---------------- pass A: gate, x_new = 2x + g*ctx, sk2 dot, mask ----------------
__global__ void k_passA(const float* __restrict__ xsrc, const int* __restrict__ mask){
    int w = (blockIdx.x*blockDim.x + threadIdx.x) >> 5;
    int lane = threadIdx.x & 31;
    if (w >= B_*L_) return;
    int b = w >> 9;
    const float* xr = xsrc + (size_t)w*D_;
    float xv[24];
    float d1 = 0.f;
#pragma unroll
    for (int j = 0; j < 24; j++){
        int e = lane + j*32;
        xv[j] = xr[e];
        d1 += xv[j]*g_gv[e];
    }
    d1 = warpsum(d1);
    float g = sigm(d1 + g_gc[b]);
    float* xo = g_x + (size_t)w*D_;
    const float* ctx = g_ctx + b*D_;
    float d2 = 0.f;
#pragma unroll
    for (int j = 0; j < 24; j++){
        int e = lane + j*32;
        float xn = 2.f*xv[j] + g*ctx[e];
        xo[e] = xn;
        d2 += xn * g_kv[D_+e];
    }
    d2 = warpsum(d2);
    if (!lane) g_sk2[w] = mask[w] ? d2 : -1e30f;
}

// ---------------- masked softmax over L; also zero gc for RA2 ----------------
__global__ void k_softmax2(){
    int b = blockIdx.x, tid = threadIdx.x;  // 512
    __shared__ float sm[16];
    __shared__ float bc;
    if (tid == 0) g_gc[b] = 0.f;
    float v = g_sk2[b*L_+tid];
    float m = warpmax(v);
    if ((tid & 31) == 0) sm[tid>>5] = m;
    __syncthreads();
    if (tid == 0){
        float mm = sm[0];
        for (int i = 1; i < 16; i++) mm = fmaxf(mm, sm[i]);
        bc = mm;
    }
    __syncthreads();
    float e = expf(v - bc);
    float s = warpsum(e);
    __syncthreads();
    if ((tid & 31) == 0) sm[tid>>5] = s;
    __syncthreads();
    if (tid == 0){
        float ss = 0.f;
        for (int i = 0; i < 16; i++) ss += sm[i];
        bc = ss;
    }
    __syncthreads();
    g_a2[b*L_+tid] = e / bc;
}

// ---------------- possum + zero lacc ----------------
__global__ void k_possum(const float* __restrict__ pos1, const float* __restrict__ pos2){
    int b = blockIdx.x, tid = threadIdx.x;  // 512
    int gidx = b*512 + tid;
    if (gidx < GM) g_lacc[gidx] = 0.f;
    __shared__ float sm1[16], sm2[16];
    float v1 = pos1[b*L_+tid], v2 = pos2[b*L_+tid];
    v1 = warpsum(v1); v2 = warpsum(v2);
    if ((tid & 31) == 0){ sm1[tid>>5] = v1; sm2[tid>>5] = v2; }
    __syncthreads();
    if (tid == 0){
        float s1 = 0.f, s2 = 0.f;
        for (int i = 0; i < 16; i++){ s1 += sm1[i]; s2 += sm2[i]; }
        g_possum[b] = s1; g_possum[B_+b] = s2;
    }
}

// ---------------- pass B: u2 = a2 @ x partials (+ pooled e1/e2 last layer) ----------------
__global__ void k_passB_part(const float* __restrict__ pos1, const float* __restrict__ pos2, int pool){
    int blk = blockIdx.x; int b = blk >> 2, ch = blk & 3;
    int t = threadIdx.x;  // 768
    __shared__ float sa[128], s1[128], s2[128];
    if (t < 128){
        int l = ch*128 + t;
        sa[t] = g_a2[b*L_+l];
        if (pool){ s1[t] = pos1[b*L_+l]; s2[t] = pos2[b*L_+l]; }
    }
    __syncthreads();
    const float* xb = g_x + ((size_t)b*L_ + ch*128)*D_ + t;
    float au = 0.f, ae1 = 0.f, ae2 = 0.f;
    for (int l = 0; l < 128; l++){
        float xv = xb[(size_t)l*D_];
        au += sa[l]*xv;
        if (pool){ ae1 += s1[l]*xv; ae2 += s2[l]*xv; }
    }
    g_bpart[((0*4+ch)*B_ + b)*D_ + t] = au;
    if (pool){
        g_bpart[((1*4+ch)*B_ + b)*D_ + t] = ae1;
        g_bpart[((2*4+ch)*B_ + b)*D_ + t] = ae2;
    }
}

// ---------------- p update ----------------
__global__ void k_pupd(){
    int w = (blockIdx.x*blockDim.x + threadIdx.x) >> 5;
    int lane = threadIdx.x & 31;
    if (w >= B_*C_) return;
    int b = w / C_;
    float* pr = g_p + (size_t)w*D_;
    float pv[24];
    float d1 = 0.f;
#pragma unroll
    for (int j = 0; j < 24; j++){
        int e = lane + j*32;
        pv[j] = pr[e];
        d1 += pv[j]*g_gv[D_+e];
    }
    d1 = warpsum(d1);
    float g = sigm(d1 + g_gc[b]);
    const float* ctx = g_ctx + b*D_;
#pragma unroll
    for (int j = 0; j < 24; j++){
        int e = lane + j*32;
        pr[e] = 2.f*pv[j] + g*ctx[e];
    }
}

// ---------------- TF32 tensor-core GEMM, fused tanh+t1+logits partial ----------------
// lacc[m] += sum_n tanh(P[m,:]@W[:,n] + t1[b(m),n]) * fc2w[n]
__global__ void __launch_bounds__(256) k_gemmH(const float* __restrict__ W,
                                               const float* __restrict__ fc2w){
    __shared__ unsigned As[2][128][20];   // m-major, KC=16, pad->stride 20 (conflict-free a-frags)
    __shared__ unsigned Bs[2][16][132];   // k-major, pad->stride 132
    int tid = threadIdx.x;
    int lane = tid & 31, g = lane >> 2, tg = lane & 3;
    int wid = tid >> 5, wm = wid >> 2, wn = wid & 3;
    int m0 = blockIdx.y * 128, n0 = blockIdx.x * 128;

    float cacc[4][4][4];
#pragma unroll
    for (int i = 0; i < 4; i++)
#pragma unroll
        for (int j = 0; j < 4; j++)
#pragma unroll
            for (int q = 0; q < 4; q++) cacc[i][j][q] = 0.f;

    int a_r = tid >> 2;          // 0..63 (rows +0/+64)
    int a_c = (tid & 3) * 4;
    int b_r = tid >> 5;          // 0..7 (rows +0/+8)
    int b_c = (tid & 31) * 4;

    float4 pa[2], pb[2];
    // prologue load chunk 0
#pragma unroll
    for (int r = 0; r < 2; r++){
        int m = m0 + a_r + r*64;
        pa[r] = (m < GM) ? *(const float4*)(g_p + (size_t)m*768 + a_c)
                         : make_float4(0.f,0.f,0.f,0.f);
        pb[r] = *(const float4*)(W + (size_t)(b_r + r*8)*768 + n0 + b_c);
    }
#pragma unroll
    for (int r = 0; r < 2; r++){
        uint4 ua = { f2tf(pa[r].x), f2tf(pa[r].y), f2tf(pa[r].z), f2tf(pa[r].w) };
        *(uint4*)&As[0][a_r + r*64][a_c] = ua;
        uint4 ub = { f2tf(pb[r].x), f2tf(pb[r].y), f2tf(pb[r].z), f2tf(pb[r].w) };
        *(uint4*)&Bs[0][b_r + r*8][b_c] = ub;
    }
    __syncthreads();

    for (int kc = 0; kc < 48; kc++){
        int cur = kc & 1;
        if (kc < 47){
            int kg = (kc+1)*16;
#pragma unroll
            for (int r = 0; r < 2; r++){
                int m = m0 + a_r + r*64;
                pa[r] = (m < GM) ? *(const float4*)(g_p + (size_t)m*768 + kg + a_c)
                                 : make_float4(0.f,0.f,0.f,0.f);
                pb[r] = *(const float4*)(W + (size_t)(kg + b_r + r*8)*768 + n0 + b_c);
            }
        }
#pragma unroll
        for (int ks = 0; ks < 2; ks++){
            int k8 = ks*8;
            unsigned af[4][4], bf[4][2];
#pragma unroll
            for (int i = 0; i < 4; i++){
                int r = wm*64 + i*16 + g;
                af[i][0] = As[cur][r][k8+tg];
                af[i][1] = As[cur][r+8][k8+tg];
                af[i][2] = As[cur][r][k8+tg+4];
                af[i][3] = As[cur][r+8][k8+tg+4];
            }
#pragma unroll
            for (int j = 0; j < 4; j++){
                int c0 = wn*32 + j*8 + g;
                bf[j][0] = Bs[cur][k8+tg][c0];
                bf[j][1] = Bs[cur][k8+tg+4][c0];
            }
#pragma unroll
            for (int i = 0; i < 4; i++)
#pragma unroll
                for (int j = 0; j < 4; j++)
                    mma_tf32(cacc[i][j], af[i][0], af[i][1], af[i][2], af[i][3],
                             bf[j][0], bf[j][1]);
        }
        if (kc < 47){
            int nxt = cur ^ 1;
#pragma unroll
            for (int r = 0; r < 2; r++){
                uint4 ua = { f2tf(pa[r].x), f2tf(pa[r].y), f2tf(pa[r].z), f2tf(pa[r].w) };
                *(uint4*)&As[nxt][a_r + r*64][a_c] = ua;
                uint4 ub = { f2tf(pb[r].x), f2tf(pb[r].y), f2tf(pb[r].z), f2tf(pb[r].w) };
                *(uint4*)&Bs[nxt][b_r + r*8][b_c] = ub;
            }
        }
        __syncthreads();
    }

    // epilogue: tanh(+t1) then partial logits dot with fc2w
#pragma unroll
    for (int i = 0; i < 4; i++){
#pragma unroll
        for (int half = 0; half < 2; half++){
            int m = m0 + wm*64 + i*16 + g + half*8;
            if (m < GM){
                int b = m / C_;
                const float* t1r = g_t1 + b*D_;
                float part = 0.f;
#pragma unroll
                for (int j = 0; j < 4; j++){
                    int n = n0 + wn*32 + j*8 + 2*tg;
                    float h0 = tanhf(cacc[i][j][half*2+0] + t1r[n]);
                    float h1 = tanhf(cacc[i][j][half*2+1] + t1r[n+1]);
                    part += h0*fc2w[n] + h1*fc2w[n+1];
                }
                part += __shfl_xor_sync(0xffffffffu, part, 1);
                part += __shfl_xor_sync(0xffffffffu, part, 2);
                if (tg == 0) atomicAdd(&g_lacc[m], part);
            } else {
                // keep shfl participation uniform
                float part = 0.f;
                part += __shfl_xor_sync(0xffffffffu, part, 1);
                part += __shfl_xor_sync(0xffffffffu, part, 2);
            }
        }
    }
}

// ---------------- final: sigmoid + write logits + argmax ----------------
__global__ void k_final(const float* __restrict__ fc2b, float* __restrict__ out,
                        int wlog, int predoff){
    __shared__ float lg[C_];
    int b = blockIdx.x, tid = threadIdx.x;  // 128
    if (tid < C_){
        float v = sigm(g_lacc[b*C_+tid] + fc2b[0]);
        lg[tid] = v;
        if (wlog) out[b*C_+tid] = v;
    }
    __syncthreads();
    if (tid == 0 && predoff >= 0){
        float best = lg[0]; int bi = 0;
        for (int c = 1; c < C_; c++)
            if (lg[c] > best){ best = lg[c]; bi = c; }
        out[predoff + b] = (float)bi;
    }
}

// ---------------- host orchestration ----------------
extern "C" void kernel_launch(void* const* d_in, const int* in_sizes, int n_in,
                              void* d_out, int out_size){
    (void)in_sizes; (void)n_in;
    const float* x_in  = (const float*)d_in[0];
    const float* pos1  = (const float*)d_in[1];
    const float* pos2  = (const float*)d_in[2];
    const int*   mask  = (const int*)  d_in[3];
    const float* emb   = (const float*)d_in[4];
    const float* rel_w = (const float*)d_in[5];
    const float* rel_b = (const float*)d_in[6];
    // d_in[7] qw, d_in[8] qb: dead (softmax separability); d_in[10] kb, d_in[14] sb: cancel
    const float* kw    = (const float*)d_in[9];
    const float* vw    = (const float*)d_in[11];
    const float* vb    = (const float*)d_in[12];
    const float* sw    = (const float*)d_in[13];
    const float* gw    = (const float*)d_in[15];
    const float* gb    = (const float*)d_in[16];
    const float* fc1w  = (const float*)d_in[17];
    const float* fc1b  = (const float*)d_in[18];
    const float* fc2w  = (const float*)d_in[19];
    const float* fc2b  = (const float*)d_in[20];
    float* out = (float*)d_out;

    float *p_p0, *p_x, *p_u, *p_ctx, *p_t1;
    cudaGetSymbolAddress((void**)&p_p0,  g_p0);
    cudaGetSymbolAddress((void**)&p_x,   g_x);
    cudaGetSymbolAddress((void**)&p_u,   g_u);
    cudaGetSymbolAddress((void**)&p_ctx, g_ctx);
    cudaGetSymbolAddress((void**)&p_t1,  g_t1);

    k_possum<<<B_,512>>>(pos1, pos2);                       // + zero lacc
    k_smgemm_part<<<dim3(12,12,4),64>>>(emb, C_, 768, rel_w, 0);
    k_smgemm_red<<<(C_*768+255)/256,256>>>(p_p0, rel_b, C_, 12, nullptr, nullptr);
    k_bcast_p<<<(B_*C_*D_/4+255)/256,256>>>();

    for (int li = 0; li < 2; li++){
        k_prep<<<192,256>>>(kw, sw, gw, li);                // + zero gc (RA1)
        // --- RA1 (queries=x, kv=p) ---
        k_ra1<<<B_,256>>>();
        k_smgemm_part<<<dim3(12,12,1),64>>>(p_u, B_, 768, vw + (size_t)(li*2+0)*D_*D_, 0);
        k_smgemm_red<<<96,256>>>(p_ctx, vb + (li*2+0)*D_, B_, 12,
                                 gw + (size_t)(li*2+0)*2*D_, gb + (li*2+0));
        k_passA<<<(B_*L_+7)/8,256>>>(li == 0 ? x_in : (const float*)p_x, mask);
        // --- RA2 (queries=p, kv=x_new, masked) ---
        k_softmax2<<<B_,512>>>();                           // + zero gc (RA2)
        k_passB_part<<<B_*4,768>>>(pos1, pos2, li == 1);
        k_smgemm_part<<<dim3(12,12,1),64>>>(nullptr, B_, 768, vw + (size_t)(li*2+1)*D_*D_, 1);
        k_smgemm_red<<<96,256>>>(p_ctx, vb + (li*2+1)*D_, B_, 12,
                                 gw + (size_t)(li*2+1)*2*D_, gb + (li*2+1));
        k_pupd<<<(B_*C_+7)/8,256>>>();
    }

    // t1 = [e1|e2] @ fc1_w[768:2304] + fc1_b
    k_smgemm_part<<<dim3(12,24,1),64>>>(nullptr, B_, 1536, fc1w + (size_t)768*768, 2);
    k_smgemm_red<<<96,256>>>(p_t1, fc1b, B_, 24, nullptr, nullptr);
    // fused: lacc += tanh(p@fc1w[:768] + t1) @ fc2w   (TF32 tensor cores)
    k_gemmH<<<dim3(6,25),256>>>(fc1w, fc2w);

    int wlog = (out_size >= B_*C_) ? 1 : 0;
    int predoff = -1;
    if (out_size >= B_*C_ + B_) predoff = B_*C_;
    else if (out_size == B_){ predoff = 0; wlog = 0; }
    k_final<<<B_,128>>>(fc2b, out, wlog, predoff);
}

// round 4
// speedup vs baseline: 1.3378x; 1.1809x over previous
#include <cuda_runtime.h>
#include <math.h>

#define B_ 32
#define L_ 512
#define D_ 768
#define C_ 97
#define GM (B_*C_)      // 3104
#define BL (B_*L_)      // 16384

// ---------------- scalar slot map (g_sc) ----------------
// 0:possum1[32] 32:possum2 64:gcA_l0 96:gcA_l1 128:cK11=ctxA0.kv01 160:cK21b=ctxA1.kv11
// 192:cG20=ctxA0.gv10 224:cK21=ctxA0.kv11 256:gc2_l0 288:gc2_l1
// 320:sag1=sum a*g0 (l0) 352:sag2a=sum a*g0 (l1) 384:sag2b=sum a*g1 (l1)
// 416:P1g0 448:P2g0 480:P1g1 512:P2g1
#define NSC 544

// ---------------- scratch ----------------
__device__ float g_p[GM*D_];
__device__ float g_p0[C_*D_];
__device__ float g_gpart[24*128*768];
__device__ float g_bpart[12*B_*D_];   // grp0(0..3): a2@x0 chunks; grp1(4..7): pos1.x0; grp2(8..11): pos2.x0
__device__ float g_kv[4*D_];          // (li,r) -> (li*2+r)*D
__device__ float g_gv[4*D_];
__device__ float g_R[4*BL];           // x0.gv(0,0), x0.kv(0,1), x0.gv(1,0), x0.kv(1,1)
__device__ float g_g0[BL];
__device__ float g_a2[BL];
__device__ float g_u[B_*D_];
__device__ float g_ctxA[2*B_*D_];     // RA1 ctx for layer 0 / layer 1
__device__ float g_ctx2[B_*D_];
__device__ float g_sc[NSC];
__device__ float g_t1[B_*D_];
__device__ float g_lacc[GM];

__device__ __forceinline__ float warpsum(float v){
#pragma unroll
    for (int o = 16; o > 0; o >>= 1) v += __shfl_xor_sync(0xffffffffu, v, o);
    return v;
}
__device__ __forceinline__ float warpmax(float v){
#pragma unroll
    for (int o = 16; o > 0; o >>= 1) v = fmaxf(v, __shfl_xor_sync(0xffffffffu, v, o));
    return v;
}
__device__ __forceinline__ float sigm(float z){ return 1.f/(1.f + expf(-z)); }
__device__ __forceinline__ unsigned f2tf(float f){
    unsigned u; asm("cvt.rna.tf32.f32 %0, %1;" : "=r"(u) : "f"(f)); return u;
}
__device__ __forceinline__ void mma_tf32(float c[4], unsigned a0, unsigned a1,
                                         unsigned a2, unsigned a3,
                                         unsigned b0, unsigned b1){
    asm volatile("mma.sync.aligned.m16n8k8.row.col.f32.tf32.tf32.f32 "
        "{%0,%1,%2,%3}, {%4,%5,%6,%7}, {%8,%9}, {%0,%1,%2,%3};\n"
        : "+f"(c[0]), "+f"(c[1]), "+f"(c[2]), "+f"(c[3])
        : "r"(a0), "r"(a1), "r"(a2), "r"(a3), "r"(b0), "r"(b1));
}

// ---------------- zero scalars + lacc ----------------
__global__ void k_zero(){
    int idx = blockIdx.x*blockDim.x + threadIdx.x;
    if (idx < NSC) g_sc[idx] = 0.f;
    if (idx < GM) g_lacc[idx] = 0.f;
}

// ---------------- prep all 4 RAs: kv = kw@sw2 rows, gv = gw1+gw2 ----------------
__global__ void __launch_bounds__(256) k_prepall(const float* __restrict__ kw,
                                                 const float* __restrict__ sw,
                                                 const float* __restrict__ gw){
    int gtid = blockIdx.x*blockDim.x + threadIdx.x;
    if (gtid < 4*D_){
        int ra = gtid/D_, dd = gtid%D_;
        const float* g = gw + (size_t)ra*2*D_;
        g_gv[gtid] = g[dd] + g[D_+dd];
    }
    int wid = gtid >> 5, lane = gtid & 31;
    if (wid < 4*D_){
        int ra = wid/D_, d = wid%D_;
        const float* krow = kw + ((size_t)ra*D_ + d)*D_;
        const float* s2   = sw + (size_t)ra*2*D_ + D_;
        float acc = 0.f;
        for (int e = lane; e < D_; e += 32) acc += krow[e]*s2[e];
        acc = warpsum(acc);
        if (!lane) g_kv[wid] = acc;
    }
}

// ---------------- single pass over x0: 4 row dots + pos column sums + possum ----------------
__global__ void __launch_bounds__(256) k_xprep(const float* __restrict__ x0,
                                               const float* __restrict__ pos1,
                                               const float* __restrict__ pos2){
    int blk = blockIdx.x; int b = blk >> 2, ch = blk & 3;
    int tid = threadIdx.x;   // 256
    int wid = tid >> 5, lane = tid & 31;
    int base = b*L_ + ch*128;
    // phase A: warp-per-row dots with 4 vectors (8 warps, 16 rows each)
    for (int r = wid; r < 128; r += 8){
        const float* xr = x0 + (size_t)(base+r)*D_;
        float a0=0.f, a1=0.f, a2=0.f, a3=0.f;
#pragma unroll
        for (int j = 0; j < 24; j++){
            int e = lane + j*32; float xv = xr[e];
            a0 += xv*g_gv[e];        // gv(0,0)
            a1 += xv*g_kv[D_+e];     // kv(0,1)
            a2 += xv*g_gv[2*D_+e];   // gv(1,0)
            a3 += xv*g_kv[3*D_+e];   // kv(1,1)
        }
        a0=warpsum(a0); a1=warpsum(a1); a2=warpsum(a2); a3=warpsum(a3);
        if (!lane){
            int row = base + r;
            g_R[row] = a0; g_R[BL+row] = a1; g_R[2*BL+row] = a2; g_R[3*BL+row] = a3;
        }
    }
    // phase B: pos-weighted column partial sums (3 cols per thread)
    __shared__ float s1[128], s2[128];
    if (tid < 128){ s1[tid] = pos1[base+tid]; s2[tid] = pos2[base+tid]; }
    __syncthreads();
#pragma unroll
    for (int c0 = 0; c0 < 3; c0++){
        int col = tid + c0*256;
        const float* xb = x0 + (size_t)base*D_ + col;
        float e1 = 0.f, e2 = 0.f;
        for (int l = 0; l < 128; l++){
            float xv = xb[(size_t)l*D_];
            e1 += s1[l]*xv; e2 += s2[l]*xv;
        }
        g_bpart[((4+ch)*B_ + b)*D_ + col] = e1;
        g_bpart[((8+ch)*B_ + b)*D_ + col] = e2;
    }
    if (tid == 0){
        float t1 = 0.f, t2 = 0.f;
        for (int l = 0; l < 128; l++){ t1 += s1[l]; t2 += s2[l]; }
        atomicAdd(&g_sc[b], t1); atomicAdd(&g_sc[32+b], t2);
    }
}

// ---------------- RA1 fused: scores over C, softmax, u = a@p ----------------
__global__ void __launch_bounds__(256) k_ra1(int li){
    __shared__ float a[C_];
    int b = blockIdx.x, tid = threadIdx.x;  // 256
    int w = tid >> 5, lane = tid & 31;
    const float* kvv = g_kv + (size_t)(li*2)*D_;
    for (int c = w; c < C_; c += 8){
        const float* pr = g_p + ((size_t)b*C_ + c)*D_;
        float acc = 0.f;
        for (int e = lane; e < D_; e += 32) acc += pr[e]*kvv[e];
        acc = warpsum(acc);
        if (!lane) a[c] = acc;
    }
    __syncthreads();
    if (tid == 0){
        float m = -1e30f;
        for (int c = 0; c < C_; c++) m = fmaxf(m, a[c]);
        float s = 0.f;
        for (int c = 0; c < C_; c++){ a[c] = expf(a[c]-m); s += a[c]; }
        float inv = 1.f/s;
        for (int c = 0; c < C_; c++) a[c] *= inv;
    }
    __syncthreads();
    for (int d = tid; d < D_; d += 256){
        const float* pb = g_p + (size_t)b*C_*D_ + d;
        float acc = 0.f;
        for (int c = 0; c < C_; c++) acc += a[c]*pb[(size_t)c*D_];
        g_u[b*D_+d] = acc;
    }
}

// ---------------- small-M split-K GEMM part ----------------
// amode 0: A plain [M,K]
// amode 1: u2 layer0: 2*sum4(grp0) + sag1[m]*ctxA0
// amode 3: u2 layer1: 4*sum4(grp0) + 2*sag2a[m]*ctxA0 + sag2b[m]*ctxA1
// amode 2: e12: (4*sum4(grp1|2) + 2*Pg0*ctxA0 + Pg1*ctxA1)/possum
__global__ void __launch_bounds__(64) k_smgemm_part(const float* __restrict__ A, int M, int K,
                                                    const float* __restrict__ W, int amode){
    __shared__ float As[32*64];
    int n  = blockIdx.x*64 + threadIdx.x;
    int kc = blockIdx.y;
    int m0 = blockIdx.z*32;
    for (int i = threadIdx.x; i < 32*64; i += 64){
        int mm = i >> 6, kk = i & 63;
        int m = m0 + mm, kg = kc*64 + kk;
        float v = 0.f;
        if (m < M){
            if (amode == 0) v = A[(size_t)m*K + kg];
            else if (amode == 1){
                float s = g_bpart[(0*B_+m)*D_+kg] + g_bpart[(1*B_+m)*D_+kg]
                        + g_bpart[(2*B_+m)*D_+kg] + g_bpart[(3*B_+m)*D_+kg];
                v = 2.f*s + g_sc[320+m]*g_ctxA[(size_t)m*D_+kg];
            } else if (amode == 3){
                float s = g_bpart[(0*B_+m)*D_+kg] + g_bpart[(1*B_+m)*D_+kg]
                        + g_bpart[(2*B_+m)*D_+kg] + g_bpart[(3*B_+m)*D_+kg];
                v = 4.f*s + 2.f*g_sc[352+m]*g_ctxA[(size_t)m*D_+kg]
                          + g_sc[384+m]*g_ctxA[(size_t)(B_+m)*D_+kg];
            } else {
                int grp = (kg < 768) ? 4 : 8;
                int kg2 = (kg < 768) ? kg : kg - 768;
                float s = g_bpart[((grp+0)*B_+m)*D_+kg2] + g_bpart[((grp+1)*B_+m)*D_+kg2]
                        + g_bpart[((grp+2)*B_+m)*D_+kg2] + g_bpart[((grp+3)*B_+m)*D_+kg2];
                float pg0 = (kg < 768) ? g_sc[416+m] : g_sc[448+m];
                float pg1 = (kg < 768) ? g_sc[480+m] : g_sc[512+m];
                float ps  = (kg < 768) ? g_sc[m]     : g_sc[32+m];
                v = (4.f*s + 2.f*pg0*g_ctxA[(size_t)m*D_+kg2]
                           + pg1*g_ctxA[(size_t)(B_+m)*D_+kg2]) / ps;
            }
        }
        As[i] = v;
    }
    __syncthreads();
    float acc[32];
#pragma unroll
    for (int i = 0; i < 32; i++) acc[i] = 0.f;
    const float* Wp = W + (size_t)(kc*64)*768 + n;
#pragma unroll 4
    for (int kk = 0; kk < 64; kk++){
        float w = Wp[(size_t)kk*768];
#pragma unroll
        for (int mm = 0; mm < 32; mm++) acc[mm] += As[mm*64+kk]*w;
    }
    float* outp = g_gpart + ((size_t)kc*128 + m0)*768 + n;
#pragma unroll
    for (int mm = 0; mm < 32; mm++) outp[(size_t)mm*768] = acc[mm];
}

// ---------------- split-K reduce + bias + up to 4 scalar dots into g_sc ----------------
__global__ void __launch_bounds__(256) k_red(float* __restrict__ out, const float* __restrict__ bias,
                      int M, int kch,
                      const float* __restrict__ v0, const float* __restrict__ gbp, int s0,
                      const float* __restrict__ v1, int s1,
                      const float* __restrict__ v2, int s2,
                      const float* __restrict__ v3, int s3){
    int idx = blockIdx.x*blockDim.x + threadIdx.x;
    if (idx >= M*768) return;
    int m = idx / 768, n = idx - m*768;
    float s = bias ? bias[n] : 0.f;
    for (int kc = 0; kc < kch; kc++) s += g_gpart[((size_t)kc*128 + m)*768 + n];
    out[idx] = s;
    int lane = threadIdx.x & 31;
    if (v0){
        float p = s*v0[n]; p = warpsum(p);
        if (!lane) atomicAdd(&g_sc[s0+m], p + ((n == 0) ? gbp[0] : 0.f));
    }
    if (v1){ float p = s*v1[n]; p = warpsum(p); if (!lane) atomicAdd(&g_sc[s1+m], p); }
    if (v2){ float p = s*v2[n]; p = warpsum(p); if (!lane) atomicAdd(&g_sc[s2+m], p); }
    if (v3){ float p = s*v3[n]; p = warpsum(p); if (!lane) atomicAdd(&g_sc[s3+m], p); }
}

__global__ void k_bcast_p(){
    int idx = blockIdx.x*blockDim.x + threadIdx.x;
    const int Q = C_*D_/4;
    if (idx >= B_*Q) return;
    ((float4*)g_p)[idx] = ((const float4*)g_p0)[idx % Q];
}

// ---------------- gates + masked softmax + scalar reductions ----------------
__global__ void __launch_bounds__(512) k_gates(int li, const int* __restrict__ mask,
                        const float* __restrict__ pos1, const float* __restrict__ pos2){
    int b = blockIdx.x, tid = threadIdx.x;   // 512
    int row = b*L_ + tid;
    float g, sk, g0v = 0.f;
    if (li == 0){
        g = sigm(g_R[row] + g_sc[64+b]);
        sk = 2.f*g_R[BL+row] + g*g_sc[128+b];
        g_g0[row] = g;
    } else {
        g0v = g_g0[row];
        g = sigm(2.f*g_R[2*BL+row] + g0v*g_sc[192+b] + g_sc[96+b]);
        sk = 4.f*g_R[3*BL+row] + 2.f*g0v*g_sc[224+b] + g*g_sc[160+b];
    }
    if (!mask[row]) sk = -1e30f;
    __shared__ float sm[16];
    __shared__ float bc;
    float m = warpmax(sk);
    if ((tid & 31) == 0) sm[tid>>5] = m;
    __syncthreads();
    if (tid == 0){
        float mm = sm[0];
        for (int i = 1; i < 16; i++) mm = fmaxf(mm, sm[i]);
        bc = mm;
    }
    __syncthreads();
    float e = expf(sk - bc);
    float ssum = warpsum(e);
    __syncthreads();
    if ((tid & 31) == 0) sm[tid>>5] = ssum;
    __syncthreads();
    if (tid == 0){
        float ss = 0.f;
        for (int i = 0; i < 16; i++) ss += sm[i];
        bc = ss;
    }
    __syncthreads();
    float a = e / bc;
    g_a2[row] = a;
    __shared__ float red[16][4];
    float rg = a*g, rg0 = a*g0v, rp1 = pos1[row]*g, rp2 = pos2[row]*g;
    rg = warpsum(rg); rg0 = warpsum(rg0); rp1 = warpsum(rp1); rp2 = warpsum(rp2);
    if ((tid & 31) == 0){
        int w = tid>>5;
        red[w][0]=rg; red[w][1]=rg0; red[w][2]=rp1; red[w][3]=rp2;
    }
    __syncthreads();
    if (tid == 0){
        float t0=0,t1=0,t2=0,t3=0;
        for (int i = 0; i < 16; i++){ t0+=red[i][0]; t1+=red[i][1]; t2+=red[i][2]; t3+=red[i][3]; }
        if (li == 0){ g_sc[320+b]=t0; g_sc[416+b]=t2; g_sc[448+b]=t3; }
        else        { g_sc[384+b]=t0; g_sc[352+b]=t1; g_sc[480+b]=t2; g_sc[512+b]=t3; }
    }
}

// ---------------- passB: a2 @ x0 partials (x0 mostly L2-resident) ----------------
__global__ void __launch_bounds__(256) k_passB(const float* __restrict__ x0){
    int blk = blockIdx.x; int b = blk >> 2, ch = blk & 3;
    int tid = threadIdx.x;  // 256
    __shared__ float sa[128];
    if (tid < 128) sa[tid] = g_a2[b*L_ + ch*128 + tid];
    __syncthreads();
#pragma unroll
    for (int c0 = 0; c0 < 3; c0++){
        int col = tid + c0*256;
        const float* xb = x0 + ((size_t)b*L_ + ch*128)*D_ + col;
        float au = 0.f;
        for (int l = 0; l < 128; l++) au += sa[l]*xb[(size_t)l*D_];
        g_bpart[((0*4+ch)*B_ + b)*D_ + col] = au;
    }
}

// ---------------- p update ----------------
__global__ void __launch_bounds__(256) k_pupd(int li){
    int w = (blockIdx.x*blockDim.x + threadIdx.x) >> 5;
    int lane = threadIdx.x & 31;
    if (w >= GM) return;
    int b = w / C_;
    float* pr = g_p + (size_t)w*D_;
    const float* gvv = g_gv + (size_t)(li*2+1)*D_;
    float pv[24];
    float d1 = 0.f;
#pragma unroll
    for (int j = 0; j < 24; j++){
        int e = lane + j*32;
        pv[j] = pr[e];
        d1 += pv[j]*gvv[e];
    }
    d1 = warpsum(d1);
    float g = sigm(d1 + g_sc[256+32*li+b]);
    const float* ctx = g_ctx2 + b*D_;
#pragma unroll
    for (int j = 0; j < 24; j++){
        int e = lane + j*32;
        pr[e] = 2.f*pv[j] + g*ctx[e];
    }
}

// ---------------- TF32 GEMM: lacc[m] += sum_n tanh(P@W1 + t1)*fc2w[n] ----------------
__global__ void __launch_bounds__(256) k_gemmH(const float* __restrict__ W,
                                               const float* __restrict__ fc2w){
    __shared__ unsigned As[2][128][20];
    __shared__ unsigned Bs[2][16][132];
    int tid = threadIdx.x;
    int lane = tid & 31, g = lane >> 2, tg = lane & 3;
    int wid = tid >> 5, wm = wid >> 2, wn = wid & 3;
    int m0 = blockIdx.y * 128, n0 = blockIdx.x * 128;

    float cacc[4][4][4];
#pragma unroll
    for (int i = 0; i < 4; i++)
#pragma unroll
        for (int j = 0; j < 4; j++)
#pragma unroll
            for (int q = 0; q < 4; q++) cacc[i][j][q] = 0.f;

    int a_r = tid >> 2, a_c = (tid & 3) * 4;
    int b_r = tid >> 5, b_c = (tid & 31) * 4;

    float4 pa[2], pb[2];
#pragma unroll
    for (int r = 0; r < 2; r++){
        int m = m0 + a_r + r*64;
        pa[r] = (m < GM) ? *(const float4*)(g_p + (size_t)m*768 + a_c)
                         : make_float4(0.f,0.f,0.f,0.f);
        pb[r] = *(const float4*)(W + (size_t)(b_r + r*8)*768 + n0 + b_c);
    }
#pragma unroll
    for (int r = 0; r < 2; r++){
        uint4 ua = { f2tf(pa[r].x), f2tf(pa[r].y), f2tf(pa[r].z), f2tf(pa[r].w) };
        *(uint4*)&As[0][a_r + r*64][a_c] = ua;
        uint4 ub = { f2tf(pb[r].x), f2tf(pb[r].y), f2tf(pb[r].z), f2tf(pb[r].w) };
        *(uint4*)&Bs[0][b_r + r*8][b_c] = ub;
    }
    __syncthreads();

    for (int kc = 0; kc < 48; kc++){
        int cur = kc & 1;
        if (kc < 47){
            int kg = (kc+1)*16;
#pragma unroll
            for (int r = 0; r < 2; r++){
                int m = m0 + a_r + r*64;
                pa[r] = (m < GM) ? *(const float4*)(g_p + (size_t)m*768 + kg + a_c)
                                 : make_float4(0.f,0.f,0.f,0.f);
                pb[r] = *(const float4*)(W + (size_t)(kg + b_r + r*8)*768 + n0 + b_c);
            }
        }
#pragma unroll
        for (int ks = 0; ks < 2; ks++){
            int k8 = ks*8;
            unsigned af[4][4], bf[4][2];
#pragma unroll
            for (int i = 0; i < 4; i++){
                int r = wm*64 + i*16 + g;
                af[i][0] = As[cur][r][k8+tg];
                af[i][1] = As[cur][r+8][k8+tg];
                af[i][2] = As[cur][r][k8+tg+4];
                af[i][3] = As[cur][r+8][k8+tg+4];
            }
#pragma unroll
            for (int j = 0; j < 4; j++){
                int c0 = wn*32 + j*8 + g;
                bf[j][0] = Bs[cur][k8+tg][c0];
                bf[j][1] = Bs[cur][k8+tg+4][c0];
            }
#pragma unroll
            for (int i = 0; i < 4; i++)
#pragma unroll
                for (int j = 0; j < 4; j++)
                    mma_tf32(cacc[i][j], af[i][0], af[i][1], af[i][2], af[i][3],
                             bf[j][0], bf[j][1]);
        }
        if (kc < 47){
            int nxt = cur ^ 1;
#pragma unroll
            for (int r = 0; r < 2; r++){
                uint4 ua = { f2tf(pa[r].x), f2tf(pa[r].y), f2tf(pa[r].z), f2tf(pa[r].w) };
                *(uint4*)&As[nxt][a_r + r*64][a_c] = ua;
                uint4 ub = { f2tf(pb[r].x), f2tf(pb[r].y), f2tf(pb[r].z), f2tf(pb[r].w) };
                *(uint4*)&Bs[nxt][b_r + r*8][b_c] = ub;
            }
        }
        __syncthreads();
    }

#pragma unroll
    for (int i = 0; i < 4; i++){
#pragma unroll
        for (int half = 0; half < 2; half++){
            int m = m0 + wm*64 + i*16 + g + half*8;
            if (m < GM){
                int b = m / C_;
                const float* t1r = g_t1 + b*D_;
                float part = 0.f;
#pragma unroll
                for (int j = 0; j < 4; j++){
                    int n = n0 + wn*32 + j*8 + 2*tg;
                    float h0 = tanhf(cacc[i][j][half*2+0] + t1r[n]);
                    float h1 = tanhf(cacc[i][j][half*2+1] + t1r[n+1]);
                    part += h0*fc2w[n] + h1*fc2w[n+1];
                }
                part += __shfl_xor_sync(0xffffffffu, part, 1);
                part += __shfl_xor_sync(0xffffffffu, part, 2);
                if (tg == 0) atomicAdd(&g_lacc[m], part);
            } else {
                float part = 0.f;
                part += __shfl_xor_sync(0xffffffffu, part, 1);
                part += __shfl_xor_sync(0xffffffffu, part, 2);
            }
        }
    }
}

// ---------------- final: sigmoid + logits + argmax ----------------
__global__ void k_final(const float* __restrict__ fc2b, float* __restrict__ out,
                        int wlog, int predoff){
    __shared__ float lg[C_];
    int b = blockIdx.x, tid = threadIdx.x;  // 128
    if (tid < C_){
        float v = sigm(g_lacc[b*C_+tid] + fc2b[0]);
        lg[tid] = v;
        if (wlog) out[b*C_+tid] = v;
    }
    __syncthreads();
    if (tid == 0 && predoff >= 0){
        float best = lg[0]; int bi = 0;
        for (int c = 1; c < C_; c++)
            if (lg[c] > best){ best = lg[c]; bi = c; }
        out[predoff + b] = (float)bi;
    }
}

// ---------------- host orchestration ----------------
extern "C" void kernel_launch(void* const* d_in, const int* in_sizes, int n_in,
                              void* d_out, int out_size){
    (void)in_sizes; (void)n_in;
    const float* x_in  = (const float*)d_in[0];
    const float* pos1  = (const float*)d_in[1];
    const float* pos2  = (const float*)d_in[2];
    const int*   mask  = (const int*)  d_in[3];
    const float* emb   = (const float*)d_in[4];
    const float* rel_w = (const float*)d_in[5];
    const float* rel_b = (const float*)d_in[6];
    const float* kw    = (const float*)d_in[9];
    const float* vw    = (const float*)d_in[11];
    const float* vb    = (const float*)d_in[12];
    const float* sw    = (const float*)d_in[13];
    const float* gw    = (const float*)d_in[15];
    const float* gb    = (const float*)d_in[16];
    const float* fc1w  = (const float*)d_in[17];
    const float* fc1b  = (const float*)d_in[18];
    const float* fc2w  = (const float*)d_in[19];
    const float* fc2b  = (const float*)d_in[20];
    float* out = (float*)d_out;

    float *p_p0, *p_u, *p_ctxA, *p_ctx2, *p_t1, *p_kv, *p_gv;
    cudaGetSymbolAddress((void**)&p_p0,   g_p0);
    cudaGetSymbolAddress((void**)&p_u,    g_u);
    cudaGetSymbolAddress((void**)&p_ctxA, g_ctxA);
    cudaGetSymbolAddress((void**)&p_ctx2, g_ctx2);
    cudaGetSymbolAddress((void**)&p_t1,   g_t1);
    cudaGetSymbolAddress((void**)&p_kv,   g_kv);
    cudaGetSymbolAddress((void**)&p_gv,   g_gv);

    k_zero<<<4,1024>>>();
    k_prepall<<<384,256>>>(kw, sw, gw);
    k_xprep<<<128,256>>>(x_in, pos1, pos2);

    // p0 = emb @ rel_w + rel_b; broadcast
    k_smgemm_part<<<dim3(12,12,4),64>>>(emb, C_, 768, rel_w, 0);
    k_red<<<(C_*768+255)/256,256>>>(p_p0, rel_b, C_, 12,
                                    nullptr, nullptr, 0, nullptr, 0, nullptr, 0, nullptr, 0);
    k_bcast_p<<<(B_*C_*D_/4+255)/256,256>>>();

    for (int li = 0; li < 2; li++){
        // --- RA1 (queries=x implicit, kv=p): ctxA = (a@p)@vw + vb ---
        k_ra1<<<B_,256>>>(li);
        k_smgemm_part<<<dim3(12,12,1),64>>>(p_u, B_, 768, vw + (size_t)(li*2+0)*D_*D_, 0);
        if (li == 0){
            k_red<<<96,256>>>(p_ctxA, vb + 0*D_, B_, 12,
                              gw + 0*2*D_, gb + 0, 64,      // gcA0
                              p_kv + 1*D_, 128,             // cK11
                              p_gv + 2*D_, 192,             // cG20
                              p_kv + 3*D_, 224);            // cK21
        } else {
            k_red<<<96,256>>>(p_ctxA + B_*D_, vb + 2*D_, B_, 12,
                              gw + (size_t)2*2*D_, gb + 2, 96,   // gcA1
                              p_kv + 3*D_, 160,                  // cK21b
                              nullptr, 0, nullptr, 0);
        }
        // --- RA2 (queries=p, kv=x implicit, masked) ---
        k_gates<<<B_,512>>>(li, mask, pos1, pos2);
        k_passB<<<128,256>>>(x_in);
        k_smgemm_part<<<dim3(12,12,1),64>>>(nullptr, B_, 768,
                                            vw + (size_t)(li*2+1)*D_*D_, li == 0 ? 1 : 3);
        k_red<<<96,256>>>(p_ctx2, vb + (li*2+1)*D_, B_, 12,
                          gw + (size_t)(li*2+1)*2*D_, gb + (li*2+1), 256+32*li,
                          nullptr, 0, nullptr, 0, nullptr, 0);
        k_pupd<<<(GM+7)/8,256>>>(li);
    }

    // t1 = [e1|e2] @ fc1_w[768:2304] + fc1_b
    k_smgemm_part<<<dim3(12,24,1),64>>>(nullptr, B_, 1536, fc1w + (size_t)768*768, 2);
    k_red<<<96,256>>>(p_t1, fc1b, B_, 24,
                      nullptr, nullptr, 0, nullptr, 0, nullptr, 0, nullptr, 0);
    k_gemmH<<<dim3(6,25),256>>>(fc1w, fc2w);

    int wlog = (out_size >= B_*C_) ? 1 : 0;
    int predoff = -1;
    if (out_size >= B_*C_ + B_) predoff = B_*C_;
    else if (out_size == B_){ predoff = 0; wlog = 0; }
    k_final<<<B_,128>>>(fc2b, out, wlog, predoff);
}

// round 5
// speedup vs baseline: 2.6636x; 1.9911x over previous
#include <cuda_runtime.h>
#include <math.h>

#define B_ 32
#define L_ 512
#define D_ 768
#define C_ 97
#define GM (B_*C_)
#define BL (B_*L_)

// ---------------- scalar slots ----------------
// 0:ps1[32] 32:ps2 64:sagx0 96:P1g0 128:P2g0 160:sagx1a 192:sagx1b
// 224:P1g1 256:P2g1 288:sag1p
#define NSC 544

// ---------------- scratch ----------------
__device__ float g_bpart[12*B_*D_];  // grp0: a2@x0 chunks; grp1: pos1.x0; grp2: pos2.x0
__device__ float g_kv[4*D_];
__device__ float g_gv[4*D_];
__device__ float g_R[4*BL];
__device__ float g_g0[BL];
__device__ float g_a2[BL];
__device__ float g_sc[NSC];
__device__ float g_p0[C_*D_];        // atomic out (TF32 gemm)
__device__ float g_pd[512];          // per-c dots: s0, dK10, dG01, dG11
__device__ float g_u0[D_];
__device__ float g_u1[B_*D_];
__device__ float g_ctxA0[D_];        // atomic out
__device__ float g_ctxA1[B_*D_];     // atomic out
__device__ float g_ctx2[2*B_*D_];    // atomic out (layer0, layer1)
__device__ float g_t1[B_*D_];        // atomic out
__device__ float g_pcw[161*D_];      // atomic out: rows 0-96 P0W, 97-128 CW0, 129-160 CW1

__device__ __forceinline__ float warpsum(float v){
#pragma unroll
    for (int o = 16; o > 0; o >>= 1) v += __shfl_xor_sync(0xffffffffu, v, o);
    return v;
}
__device__ __forceinline__ float warpmax(float v){
#pragma unroll
    for (int o = 16; o > 0; o >>= 1) v = fmaxf(v, __shfl_xor_sync(0xffffffffu, v, o));
    return v;
}
__device__ __forceinline__ float sigm(float z){ return 1.f/(1.f + expf(-z)); }
__device__ __forceinline__ unsigned f2tf(float f){
    unsigned u; asm("cvt.rna.tf32.f32 %0, %1;" : "=r"(u) : "f"(f)); return u;
}
__device__ __forceinline__ void mma_tf32(float c[4], unsigned a0, unsigned a1,
                                         unsigned a2, unsigned a3,
                                         unsigned b0, unsigned b1){
    asm volatile("mma.sync.aligned.m16n8k8.row.col.f32.tf32.tf32.f32 "
        "{%0,%1,%2,%3}, {%4,%5,%6,%7}, {%8,%9}, {%0,%1,%2,%3};\n"
        : "+f"(c[0]), "+f"(c[1]), "+f"(c[2]), "+f"(c[3])
        : "r"(a0), "r"(a1), "r"(a2), "r"(a3), "r"(b0), "r"(b1));
}
// block dot over 768 elems; sh must have >= nthr/32 floats
__device__ __forceinline__ float blockdot768(const float* __restrict__ a,
                                             const float* __restrict__ v,
                                             float* sh, int nthr){
    int tid = threadIdx.x, lane = tid & 31, w = tid >> 5;
    float p = 0.f;
    for (int e = tid; e < D_; e += nthr) p += a[e]*v[e];
    p = warpsum(p);
    __syncthreads();
    if (!lane) sh[w] = p;
    __syncthreads();
    float r = 0.f;
    int nw = nthr >> 5;
    for (int i = 0; i < nw; i++) r += sh[i];
    return r;
}

// ---------------- zero all atomic outputs + scalars ----------------
__global__ void k_zero(){
    int idx = blockIdx.x*blockDim.x + threadIdx.x;
    if (idx < NSC) g_sc[idx] = 0.f;
    if (idx < C_*D_) g_p0[idx] = 0.f;
    if (idx < D_) g_ctxA0[idx] = 0.f;
    if (idx < B_*D_){ g_ctxA1[idx] = 0.f; g_t1[idx] = 0.f; }
    if (idx < 2*B_*D_) g_ctx2[idx] = 0.f;
    if (idx < 161*D_) g_pcw[idx] = 0.f;
}

// ---------------- kv = kw@sw2 rows, gv = gw1+gw2, all 4 RAs ----------------
__global__ void __launch_bounds__(256) k_prepall(const float* __restrict__ kw,
                                                 const float* __restrict__ sw,
                                                 const float* __restrict__ gw){
    int gtid = blockIdx.x*blockDim.x + threadIdx.x;
    if (gtid < 4*D_){
        int ra = gtid/D_, dd = gtid%D_;
        const float* g = gw + (size_t)ra*2*D_;
        g_gv[gtid] = g[dd] + g[D_+dd];
    }
    int wid = gtid >> 5, lane = gtid & 31;
    if (wid < 4*D_){
        int ra = wid/D_, d = wid%D_;
        const float* krow = kw + ((size_t)ra*D_ + d)*D_;
        const float* s2   = sw + (size_t)ra*2*D_ + D_;
        float acc = 0.f;
        for (int e = lane; e < D_; e += 32) acc += krow[e]*s2[e];
        acc = warpsum(acc);
        if (!lane) g_kv[wid] = acc;
    }
}

// ---------------- one pass over x0: 4 row dots + pos column sums + possum ----------------
__global__ void __launch_bounds__(256) k_xprep(const float* __restrict__ x0,
                                               const float* __restrict__ pos1,
                                               const float* __restrict__ pos2){
    int blk = blockIdx.x; int b = blk >> 2, ch = blk & 3;
    int tid = threadIdx.x;
    int wid = tid >> 5, lane = tid & 31;
    int base = b*L_ + ch*128;
    for (int r = wid; r < 128; r += 8){
        const float* xr = x0 + (size_t)(base+r)*D_;
        float a0=0.f, a1=0.f, a2=0.f, a3=0.f;
#pragma unroll
        for (int j = 0; j < 24; j++){
            int e = lane + j*32; float xv = xr[e];
            a0 += xv*g_gv[e];
            a1 += xv*g_kv[D_+e];
            a2 += xv*g_gv[2*D_+e];
            a3 += xv*g_kv[3*D_+e];
        }
        a0=warpsum(a0); a1=warpsum(a1); a2=warpsum(a2); a3=warpsum(a3);
        if (!lane){
            int row = base + r;
            g_R[row] = a0; g_R[BL+row] = a1; g_R[2*BL+row] = a2; g_R[3*BL+row] = a3;
        }
    }
    __shared__ float s1[128], s2[128];
    if (tid < 128){ s1[tid] = pos1[base+tid]; s2[tid] = pos2[base+tid]; }
    __syncthreads();
#pragma unroll
    for (int c0 = 0; c0 < 3; c0++){
        int col = tid + c0*256;
        const float* xb = x0 + (size_t)base*D_ + col;
        float e1 = 0.f, e2 = 0.f;
        for (int l = 0; l < 128; l++){
            float xv = xb[(size_t)l*D_];
            e1 += s1[l]*xv; e2 += s2[l]*xv;
        }
        g_bpart[((4+ch)*B_ + b)*D_ + col] = e1;
        g_bpart[((8+ch)*B_ + b)*D_ + col] = e2;
    }
    if (tid == 0){
        float t1 = 0.f, t2 = 0.f;
        for (int l = 0; l < 128; l++){ t1 += s1[l]; t2 += s2[l]; }
        atomicAdd(&g_sc[b], t1); atomicAdd(&g_sc[32+b], t2);
    }
}

// ---------------- per-c dots of p0 with 4 vectors ----------------
__global__ void __launch_bounds__(256) k_pdots(){
    int w = (blockIdx.x*256 + threadIdx.x) >> 5;
    int lane = threadIdx.x & 31;
    if (w >= C_) return;
    const float* pr = g_p0 + (size_t)w*D_;
    float a0=0.f,a1=0.f,a2=0.f,a3=0.f;
#pragma unroll
    for (int j=0;j<24;j++){
        int e = lane + j*32; float pv = pr[e];
        a0 += pv*g_kv[e];        // kv(0,0)
        a1 += pv*g_kv[2*D_+e];   // kv(1,0)
        a2 += pv*g_gv[D_+e];     // gv(0,1)
        a3 += pv*g_gv[3*D_+e];   // gv(1,1)
    }
    a0=warpsum(a0);a1=warpsum(a1);a2=warpsum(a2);a3=warpsum(a3);
    if (!lane){ g_pd[w]=a0; g_pd[128+w]=a1; g_pd[256+w]=a2; g_pd[384+w]=a3; }
}

// ---------------- layer0 RA1 (batch-independent): u0 = softmax(s0)@p0 ----------------
__global__ void __launch_bounds__(128) k_ra1_l0(){
    __shared__ float a[C_];
    int tid = threadIdx.x;
    if (tid < C_) a[tid] = g_pd[tid];
    __syncthreads();
    if (tid == 0){
        float m = -1e30f;
        for (int c=0;c<C_;c++) m = fmaxf(m, a[c]);
        float s = 0.f;
        for (int c=0;c<C_;c++){ a[c] = expf(a[c]-m); s += a[c]; }
        float inv = 1.f/s;
        for (int c=0;c<C_;c++) a[c] *= inv;
    }
    __syncthreads();
    int n = blockIdx.x*128 + tid;
    float acc = 0.f;
    for (int c=0;c<C_;c++) acc += a[c]*g_p0[(size_t)c*D_+n];
    g_u0[n] = acc;
}

// ---------------- GEMV: ctxA0 = u0@W + bias ----------------
__global__ void __launch_bounds__(128) k_gemv(const float* __restrict__ W,
                                              const float* __restrict__ bias){
    int n = blockIdx.x*128 + threadIdx.x;
    int kc = blockIdx.y;
    float acc = (kc==0) ? bias[n] : 0.f;
    const float* Wp = W + (size_t)kc*96*D_ + n;
    const float* u = g_u0 + kc*96;
#pragma unroll 4
    for (int k=0;k<96;k++) acc += u[k]*Wp[(size_t)k*D_];
    atomicAdd(&g_ctxA0[n], acc);
}

// ---------------- gates + masked softmax over L + scalar reductions ----------------
__global__ void __launch_bounds__(512) k_gates(int li, const int* __restrict__ mask,
                        const float* __restrict__ pos1, const float* __restrict__ pos2,
                        const float* __restrict__ gwp, const float* __restrict__ gbp){
    int b = blockIdx.x, tid = threadIdx.x;
    __shared__ float sh[16];
    __shared__ float sc[4];
    if (li == 0){
        float d0 = blockdot768(g_ctxA0, gwp, sh, 512);           // gcA0 (part)
        float d1 = blockdot768(g_ctxA0, g_kv + D_, sh, 512);     // cK11
        if (tid == 0){ sc[0] = d0 + gbp[0]; sc[1] = d1; }
    } else {
        const float* cA1 = g_ctxA1 + (size_t)b*D_;
        float d0 = blockdot768(cA1, gwp, sh, 512);               // gcA1
        float d1 = blockdot768(g_ctxA0, g_gv + 2*D_, sh, 512);   // cG
        float d2 = blockdot768(g_ctxA0, g_kv + 3*D_, sh, 512);   // cK21
        float d3 = blockdot768(cA1, g_kv + 3*D_, sh, 512);       // cK21b
        if (tid == 0){ sc[0]=d0+gbp[0]; sc[1]=d1; sc[2]=d2; sc[3]=d3; }
    }
    __syncthreads();
    int row = b*L_ + tid;
    float g, sk, g0v = 0.f;
    if (li == 0){
        g = sigm(g_R[row] + sc[0]);
        sk = 2.f*g_R[BL+row] + g*sc[1];
        g_g0[row] = g;
    } else {
        g0v = g_g0[row];
        g = sigm(2.f*g_R[2*BL+row] + g0v*sc[1] + sc[0]);
        sk = 4.f*g_R[3*BL+row] + 2.f*g0v*sc[2] + g*sc[3];
    }
    if (!mask[row]) sk = -1e30f;
    __shared__ float sm[16];
    __shared__ float bc;
    float m = warpmax(sk);
    if ((tid & 31) == 0) sm[tid>>5] = m;
    __syncthreads();
    if (tid == 0){
        float mm = sm[0];
        for (int i = 1; i < 16; i++) mm = fmaxf(mm, sm[i]);
        bc = mm;
    }
    __syncthreads();
    float e = expf(sk - bc);
    float ssum = warpsum(e);
    __syncthreads();
    if ((tid & 31) == 0) sm[tid>>5] = ssum;
    __syncthreads();
    if (tid == 0){
        float ss = 0.f;
        for (int i = 0; i < 16; i++) ss += sm[i];
        bc = ss;
    }
    __syncthreads();
    float a = e / bc;
    g_a2[row] = a;
    __shared__ float red[16][4];
    float r0, r1, r2, r3;
    if (li == 0){ r0 = a*g; r1 = pos1[row]*g; r2 = pos2[row]*g; r3 = 0.f; }
    else        { r0 = a*g0v; r1 = a*g; r2 = pos1[row]*g; r3 = pos2[row]*g; }
    r0=warpsum(r0); r1=warpsum(r1); r2=warpsum(r2); r3=warpsum(r3);
    if ((tid & 31) == 0){
        int w = tid>>5;
        red[w][0]=r0; red[w][1]=r1; red[w][2]=r2; red[w][3]=r3;
    }
    __syncthreads();
    if (tid == 0){
        float t0=0,t1=0,t2=0,t3=0;
        for (int i = 0; i < 16; i++){ t0+=red[i][0]; t1+=red[i][1]; t2+=red[i][2]; t3+=red[i][3]; }
        if (li == 0){ g_sc[64+b]=t0; g_sc[96+b]=t1; g_sc[128+b]=t2; }
        else        { g_sc[160+b]=t0; g_sc[192+b]=t1; g_sc[224+b]=t2; g_sc[256+b]=t3; }
    }
}

// ---------------- passB: a2 @ x0 partials ----------------
__global__ void __launch_bounds__(256) k_passB(const float* __restrict__ x0){
    int blk = blockIdx.x; int b = blk >> 2, ch = blk & 3;
    int tid = threadIdx.x;
    __shared__ float sa[128];
    if (tid < 128) sa[tid] = g_a2[b*L_ + ch*128 + tid];
    __syncthreads();
#pragma unroll
    for (int c0 = 0; c0 < 3; c0++){
        int col = tid + c0*256;
        const float* xb = x0 + ((size_t)b*L_ + ch*128)*D_ + col;
        float au = 0.f;
        for (int l = 0; l < 128; l++) au += sa[l]*xb[(size_t)l*D_];
        g_bpart[(ch*B_ + b)*D_ + col] = au;
    }
}

// ---------------- layer1 RA1: per-b softmax over C + u1 row ----------------
__global__ void __launch_bounds__(256) k_ra1_l1(const float* __restrict__ gwp,
                                                const float* __restrict__ gbp){
    int b = blockIdx.x, tid = threadIdx.x;
    __shared__ float sh[8];
    __shared__ float sc2[2];
    __shared__ float a1[C_], g0p[C_];
    __shared__ float sag;
    const float* c20 = g_ctx2 + (size_t)b*D_;
    float d0 = blockdot768(c20, gwp, sh, 256);          // gc2_0 (part)
    float d1 = blockdot768(c20, g_kv + 2*D_, sh, 256);  // cB0
    if (tid == 0){ sc2[0] = d0 + gbp[0]; sc2[1] = d1; }
    __syncthreads();
    if (tid < C_){
        float gp = sigm(g_pd[256+tid] + sc2[0]);
        g0p[tid] = gp;
        a1[tid] = 2.f*g_pd[128+tid] + gp*sc2[1];
    }
    __syncthreads();
    if (tid == 0){
        float m = -1e30f;
        for (int c=0;c<C_;c++) m = fmaxf(m, a1[c]);
        float s = 0.f;
        for (int c=0;c<C_;c++){ a1[c] = expf(a1[c]-m); s += a1[c]; }
        float inv = 1.f/s, sg = 0.f;
        for (int c=0;c<C_;c++){ a1[c] *= inv; sg += a1[c]*g0p[c]; }
        sag = sg; g_sc[288+b] = sg;
    }
    __syncthreads();
    for (int n = tid; n < D_; n += 256){
        float s = 0.f;
        for (int c=0;c<C_;c++) s += a1[c]*g_p0[(size_t)c*D_+n];
        g_u1[b*D_+n] = 2.f*s + sag*c20[n];
    }
}

// ---------------- A-assembly for the TF32 GEMM ----------------
__device__ __forceinline__ float4 f4sum4(int grp, int m, int kg){
    float4 a = *(const float4*)(g_bpart + ((size_t)(grp+0)*B_+m)*D_ + kg);
    float4 b = *(const float4*)(g_bpart + ((size_t)(grp+1)*B_+m)*D_ + kg);
    float4 c = *(const float4*)(g_bpart + ((size_t)(grp+2)*B_+m)*D_ + kg);
    float4 d = *(const float4*)(g_bpart + ((size_t)(grp+3)*B_+m)*D_ + kg);
    return make_float4(a.x+b.x+c.x+d.x, a.y+b.y+c.y+d.y, a.z+b.z+c.z+d.z, a.w+b.w+c.w+d.w);
}
__device__ __forceinline__ float4 loadA4(const float* __restrict__ A, int amode,
                                         int m, int M, int kg, int K){
    if (m >= M) return make_float4(0.f,0.f,0.f,0.f);
    if (amode == 0) return *(const float4*)(A + (size_t)m*K + kg);
    if (amode == 1){   // u2_0 = 2*sum4(grp0) + sagx0*ctxA0
        float4 s = f4sum4(0, m, kg);
        float4 c = *(const float4*)(g_ctxA0 + kg);
        float sg = g_sc[64+m];
        return make_float4(2.f*s.x+sg*c.x, 2.f*s.y+sg*c.y, 2.f*s.z+sg*c.z, 2.f*s.w+sg*c.w);
    }
    if (amode == 2){   // u2_1 = 4*sum4 + 2*sagx1a*ctxA0 + sagx1b*ctxA1[m]
        float4 s = f4sum4(0, m, kg);
        float4 c0 = *(const float4*)(g_ctxA0 + kg);
        float4 c1 = *(const float4*)(g_ctxA1 + (size_t)m*D_ + kg);
        float sa = 2.f*g_sc[160+m], sb = g_sc[192+m];
        return make_float4(4.f*s.x+sa*c0.x+sb*c1.x, 4.f*s.y+sa*c0.y+sb*c1.y,
                           4.f*s.z+sa*c0.z+sb*c1.z, 4.f*s.w+sa*c0.w+sb*c1.w);
    }
    if (amode == 3){   // e12 = (4*sum4(grp1|2) + 2*Pg0*ctxA0 + Pg1*ctxA1[m]) / ps
        int grp = (kg < D_) ? 4 : 8;
        int k2 = (kg < D_) ? kg : kg - D_;
        float4 s = f4sum4(grp, m, k2);
        float4 c0 = *(const float4*)(g_ctxA0 + k2);
        float4 c1 = *(const float4*)(g_ctxA1 + (size_t)m*D_ + k2);
        float pg0 = 2.f*((kg < D_) ? g_sc[96+m] : g_sc[128+m]);
        float pg1 = (kg < D_) ? g_sc[224+m] : g_sc[256+m];
        float inv = 1.f/((kg < D_) ? g_sc[m] : g_sc[32+m]);
        return make_float4((4.f*s.x+pg0*c0.x+pg1*c1.x)*inv, (4.f*s.y+pg0*c0.y+pg1*c1.y)*inv,
                           (4.f*s.z+pg0*c0.z+pg1*c1.z)*inv, (4.f*s.w+pg0*c0.w+pg1*c1.w)*inv);
    }
    // amode 4: stacked [p0; ctx2_0; ctx2_1]
    if (m < 97)  return *(const float4*)(g_p0 + (size_t)m*D_ + kg);
    if (m < 129) return *(const float4*)(g_ctx2 + (size_t)(m-97)*D_ + kg);
    return *(const float4*)(g_ctx2 + (size_t)(B_+(m-129))*D_ + kg);
}

// ---------------- TF32 split-K GEMM: atomicAdd out += A@W (+bias on kb==0) ----------------
__global__ void __launch_bounds__(256) k_tcgemm(const float* __restrict__ A,
        const float* __restrict__ W, float* __restrict__ out,
        const float* __restrict__ bias, int M, int K, int KCH, int amode){
    __shared__ unsigned As[2][128][20];
    __shared__ unsigned Bs[2][16][132];
    int tid = threadIdx.x;
    int lane = tid & 31, g = lane >> 2, tg = lane & 3;
    int wid = tid >> 5, wm = wid >> 2, wn = wid & 3;
    int n0 = blockIdx.x * 128;
    int kb = blockIdx.y;
    int m0 = blockIdx.z * 128;
    int kbase = kb * KCH;
    int NS = KCH / 16;

    float cacc[4][4][4];
#pragma unroll
    for (int i = 0; i < 4; i++)
#pragma unroll
        for (int j = 0; j < 4; j++)
#pragma unroll
            for (int q = 0; q < 4; q++) cacc[i][j][q] = 0.f;

    int a_r = tid >> 2, a_c = (tid & 3) * 4;
    int b_r = tid >> 5, b_c = (tid & 31) * 4;

    float4 pa[2], pb[2];
#pragma unroll
    for (int r = 0; r < 2; r++){
        pa[r] = loadA4(A, amode, m0 + a_r + r*64, M, kbase + a_c, K);
        pb[r] = *(const float4*)(W + (size_t)(kbase + b_r + r*8)*D_ + n0 + b_c);
    }
#pragma unroll
    for (int r = 0; r < 2; r++){
        uint4 ua = { f2tf(pa[r].x), f2tf(pa[r].y), f2tf(pa[r].z), f2tf(pa[r].w) };
        *(uint4*)&As[0][a_r + r*64][a_c] = ua;
        uint4 ub = { f2tf(pb[r].x), f2tf(pb[r].y), f2tf(pb[r].z), f2tf(pb[r].w) };
        *(uint4*)&Bs[0][b_r + r*8][b_c] = ub;
    }
    __syncthreads();

    for (int s = 0; s < NS; s++){
        int cur = s & 1;
        if (s < NS-1){
            int kg = kbase + (s+1)*16;
#pragma unroll
            for (int r = 0; r < 2; r++){
                pa[r] = loadA4(A, amode, m0 + a_r + r*64, M, kg + a_c, K);
                pb[r] = *(const float4*)(W + (size_t)(kg + b_r + r*8)*D_ + n0 + b_c);
            }
        }
#pragma unroll
        for (int ks = 0; ks < 2; ks++){
            int k8 = ks*8;
            unsigned af[4][4], bf[4][2];
#pragma unroll
            for (int i = 0; i < 4; i++){
                int r = wm*64 + i*16 + g;
                af[i][0] = As[cur][r][k8+tg];
                af[i][1] = As[cur][r+8][k8+tg];
                af[i][2] = As[cur][r][k8+tg+4];
                af[i][3] = As[cur][r+8][k8+tg+4];
            }
#pragma unroll
            for (int j = 0; j < 4; j++){
                int c0 = wn*32 + j*8 + g;
                bf[j][0] = Bs[cur][k8+tg][c0];
                bf[j][1] = Bs[cur][k8+tg+4][c0];
            }
#pragma unroll
            for (int i = 0; i < 4; i++)
#pragma unroll
                for (int j = 0; j < 4; j++)
                    mma_tf32(cacc[i][j], af[i][0], af[i][1], af[i][2], af[i][3],
                             bf[j][0], bf[j][1]);
        }
        if (s < NS-1){
            int nxt = cur ^ 1;
#pragma unroll
            for (int r = 0; r < 2; r++){
                uint4 ua = { f2tf(pa[r].x), f2tf(pa[r].y), f2tf(pa[r].z), f2tf(pa[r].w) };
                *(uint4*)&As[nxt][a_r + r*64][a_c] = ua;
                uint4 ub = { f2tf(pb[r].x), f2tf(pb[r].y), f2tf(pb[r].z), f2tf(pb[r].w) };
                *(uint4*)&Bs[nxt][b_r + r*8][b_c] = ub;
            }
        }
        __syncthreads();
    }

#pragma unroll
    for (int i = 0; i < 4; i++){
#pragma unroll
        for (int half = 0; half < 2; half++){
            int m = m0 + wm*64 + i*16 + g + half*8;
            if (m < M){
#pragma unroll
                for (int j = 0; j < 4; j++){
                    int n = n0 + wn*32 + j*8 + 2*tg;
                    float v0 = cacc[i][j][half*2+0];
                    float v1 = cacc[i][j][half*2+1];
                    if (kb == 0 && bias){ v0 += bias[n]; v1 += bias[n+1]; }
                    atomicAdd(out + (size_t)m*D_ + n,     v0);
                    atomicAdd(out + (size_t)m*D_ + n + 1, v1);
                }
            }
        }
    }
}

// ---------------- final: tanh recombination + logits + argmax ----------------
__global__ void __launch_bounds__(256) k_tanh(const float* __restrict__ gw,
        const float* __restrict__ gb, const float* __restrict__ fc2w,
        const float* __restrict__ fc2b, float* __restrict__ out,
        int wlog, int predoff){
    int b = blockIdx.x, tid = threadIdx.x, lane = tid & 31, wid = tid >> 5;
    __shared__ float sh[8];
    __shared__ float cw0[D_], cw1[D_], t1s[D_], w2[D_];
    __shared__ float sc3[3];
    __shared__ float lg[C_];
    const float* c20 = g_ctx2 + (size_t)b*D_;
    const float* c21 = g_ctx2 + (size_t)(B_+b)*D_;
    for (int e = tid; e < D_; e += 256){
        cw0[e] = g_pcw[(size_t)(97+b)*D_+e];
        cw1[e] = g_pcw[(size_t)(129+b)*D_+e];
        t1s[e] = g_t1[b*D_+e];
        w2[e]  = fc2w[e];
    }
    float d0 = blockdot768(c20, gw + 1*2*D_, sh, 256);   // gc2_0 part
    float d1 = blockdot768(c20, g_gv + 3*D_, sh, 256);   // cE
    float d2 = blockdot768(c21, gw + 3*2*D_, sh, 256);   // gc2_1 part
    if (tid == 0){ sc3[0] = d0 + gb[1]; sc3[1] = d1; sc3[2] = d2 + gb[3]; }
    __syncthreads();
    for (int c = wid; c < C_; c += 8){
        float gp0 = sigm(g_pd[256+c] + sc3[0]);
        float gp1 = sigm(2.f*g_pd[384+c] + gp0*sc3[1] + sc3[2]);
        const float* pw = g_pcw + (size_t)c*D_;
        float acc = 0.f;
#pragma unroll
        for (int j = 0; j < 24; j++){
            int n = lane + j*32;
            float z = 4.f*pw[n] + 2.f*gp0*cw0[n] + gp1*cw1[n] + t1s[n];
            acc += tanhf(z)*w2[n];
        }
        acc = warpsum(acc);
        if (!lane){
            float l = sigm(acc + fc2b[0]);
            lg[c] = l;
            if (wlog) out[b*C_+c] = l;
        }
    }
    __syncthreads();
    if (tid == 0 && predoff >= 0){
        float best = lg[0]; int bi = 0;
        for (int c = 1; c < C_; c++)
            if (lg[c] > best){ best = lg[c]; bi = c; }
        out[predoff + b] = (float)bi;
    }
}

// ---------------- host orchestration ----------------
extern "C" void kernel_launch(void* const* d_in, const int* in_sizes, int n_in,
                              void* d_out, int out_size){
    (void)in_sizes; (void)n_in;
    const float* x_in  = (const float*)d_in[0];
    const float* pos1  = (const float*)d_in[1];
    const float* pos2  = (const float*)d_in[2];
    const int*   mask  = (const int*)  d_in[3];
    const float* emb   = (const float*)d_in[4];
    const float* rel_w = (const float*)d_in[5];
    const float* rel_b = (const float*)d_in[6];
    const float* kw    = (const float*)d_in[9];
    const float* vw    = (const float*)d_in[11];
    const float* vb    = (const float*)d_in[12];
    const float* sw    = (const float*)d_in[13];
    const float* gw    = (const float*)d_in[15];
    const float* gb    = (const float*)d_in[16];
    const float* fc1w  = (const float*)d_in[17];
    const float* fc1b  = (const float*)d_in[18];
    const float* fc2w  = (const float*)d_in[19];
    const float* fc2b  = (const float*)d_in[20];
    float* out = (float*)d_out;

    float *p_p0, *p_u1, *p_ctxA1, *p_ctx2, *p_t1, *p_pcw;
    cudaGetSymbolAddress((void**)&p_p0,    g_p0);
    cudaGetSymbolAddress((void**)&p_u1,    g_u1);
    cudaGetSymbolAddress((void**)&p_ctxA1, g_ctxA1);
    cudaGetSymbolAddress((void**)&p_ctx2,  g_ctx2);
    cudaGetSymbolAddress((void**)&p_t1,    g_t1);
    cudaGetSymbolAddress((void**)&p_pcw,   g_pcw);

    k_zero<<<483,256>>>();
    k_prepall<<<384,256>>>(kw, sw, gw);
    k_xprep<<<128,256>>>(x_in, pos1, pos2);

    // p0 = emb @ rel_w + rel_b
    k_tcgemm<<<dim3(6,8,1),256>>>(emb, rel_w, p_p0, rel_b, 97, 768, 96, 0);
    k_pdots<<<13,256>>>();
    // layer0 RA1 (batch-independent): ctxA0 = u0@vw00 + vb00
    k_ra1_l0<<<6,128>>>();
    k_gemv<<<dim3(6,8),128>>>(vw, vb);
    // layer0 RA2
    k_gates<<<B_,512>>>(0, mask, pos1, pos2, gw, gb);
    k_passB<<<128,256>>>(x_in);
    k_tcgemm<<<dim3(6,8,1),256>>>(nullptr, vw + (size_t)1*D_*D_, p_ctx2, vb + 1*D_, 32, 768, 96, 1);
    // layer1 RA1: u1 per-b, ctxA1 = u1@vw10 + vb10
    k_ra1_l1<<<B_,256>>>(gw + (size_t)1*2*D_, gb + 1);
    k_tcgemm<<<dim3(6,8,1),256>>>(p_u1, vw + (size_t)2*D_*D_, p_ctxA1, vb + 2*D_, 32, 768, 96, 0);
    // layer1 RA2
    k_gates<<<B_,512>>>(1, mask, pos1, pos2, gw + (size_t)2*2*D_, gb + 2);
    k_passB<<<128,256>>>(x_in);
    k_tcgemm<<<dim3(6,8,1),256>>>(nullptr, vw + (size_t)3*D_*D_, p_ctx2 + B_*D_, vb + 3*D_, 32, 768, 96, 2);
    // t1 = [e1|e2] @ fc1w[768:2304] + fc1b
    k_tcgemm<<<dim3(6,8,1),256>>>(nullptr, fc1w + (size_t)768*768, p_t1, fc1b, 32, 1536, 192, 3);
    // PCW = [p0; ctx2_0; ctx2_1] @ fc1w[0:768]
    k_tcgemm<<<dim3(6,8,2),256>>>(nullptr, fc1w, p_pcw, nullptr, 161, 768, 96, 4);

    int wlog = (out_size >= GM) ? 1 : 0;
    int predoff = -1;
    if (out_size >= GM + B_) predoff = GM;
    else if (out_size == B_){ predoff = 0; wlog = 0; }
    k_tanh<<<B_,256>>>(gw, gb, fc2w, fc2b, out, wlog, predoff);
}

// round 7
// speedup vs baseline: 2.7120x; 1.0182x over previous
#include <cuda_runtime.h>
#include <math.h>

#define B_ 32
#define L_ 512
#define D_ 768
#define C_ 97
#define GM (B_*C_)
#define BL (B_*L_)

// ---------------- scalar slots ----------------
// 0:ps1[32] 32:ps2 64:sagx0 96:P1g0 128:P2g0 160:sagx1a 192:sagx1b
// 224:P1g1 256:P2g1 288:sag1p
#define NSC 544

// ---------------- scratch ----------------
__device__ float g_bpart[12*B_*D_];
__device__ float g_kv[4*D_];
__device__ float g_gv[4*D_];
__device__ float g_R[4*BL];
__device__ float g_g0[BL];
__device__ float g_a2[BL];
__device__ float g_sc[NSC];
__device__ float g_p0[C_*D_];
__device__ float g_pd[512];
__device__ float g_u0[D_];
__device__ float g_u1[B_*D_];
__device__ float g_ctxA0[D_];
__device__ float g_ctxA1[B_*D_];
__device__ float g_ctx2[2*B_*D_];
__device__ float g_t1[B_*D_];
__device__ float g_pcw[161*D_];

__device__ __forceinline__ float warpsum(float v){
#pragma unroll
    for (int o = 16; o > 0; o >>= 1) v += __shfl_xor_sync(0xffffffffu, v, o);
    return v;
}
__device__ __forceinline__ float warpmax(float v){
#pragma unroll
    for (int o = 16; o > 0; o >>= 1) v = fmaxf(v, __shfl_xor_sync(0xffffffffu, v, o));
    return v;
}
__device__ __forceinline__ float sigm(float z){ return 1.f/(1.f + expf(-z)); }
__device__ __forceinline__ unsigned f2tf(float f){
    unsigned u; asm("cvt.rna.tf32.f32 %0, %1;" : "=r"(u) : "f"(f)); return u;
}
__device__ __forceinline__ void mma_tf32(float c[4], unsigned a0, unsigned a1,
                                         unsigned a2, unsigned a3,
                                         unsigned b0, unsigned b1){
    asm volatile("mma.sync.aligned.m16n8k8.row.col.f32.tf32.tf32.f32 "
        "{%0,%1,%2,%3}, {%4,%5,%6,%7}, {%8,%9}, {%0,%1,%2,%3};\n"
        : "+f"(c[0]), "+f"(c[1]), "+f"(c[2]), "+f"(c[3])
        : "r"(a0), "r"(a1), "r"(a2), "r"(a3), "r"(b0), "r"(b1));
}
__device__ __forceinline__ float blockdot768(const float* __restrict__ a,
                                             const float* __restrict__ v,
                                             float* sh, int nthr){
    int tid = threadIdx.x, lane = tid & 31, w = tid >> 5;
    float p = 0.f;
    for (int e = tid; e < D_; e += nthr) p += a[e]*v[e];
    p = warpsum(p);
    __syncthreads();
    if (!lane) sh[w] = p;
    __syncthreads();
    float r = 0.f;
    int nw = nthr >> 5;
    for (int i = 0; i < nw; i++) r += sh[i];
    return r;
}

// ---------------- zero p0 ----------------
__global__ void k_zp0(){
    int i = blockIdx.x*256 + threadIdx.x;
    if (i < C_*D_) g_p0[i] = 0.f;
}

// ---------------- fused: zero all other atomic outputs + prep kv/gv ----------------
__global__ void __launch_bounds__(256) k_prepzero(const float* __restrict__ kw,
                                                  const float* __restrict__ sw,
                                                  const float* __restrict__ gw){
    int gtid = blockIdx.x*blockDim.x + threadIdx.x;
    if (gtid < NSC) g_sc[gtid] = 0.f;
    if (gtid < D_) g_ctxA0[gtid] = 0.f;
    if (gtid < B_*D_){ g_ctxA1[gtid] = 0.f; g_t1[gtid] = 0.f; }
    if (gtid < 2*B_*D_) g_ctx2[gtid] = 0.f;
    if (gtid < 161*D_) g_pcw[gtid] = 0.f;
    if (gtid < 4*D_){
        int ra = gtid/D_, dd = gtid%D_;
        const float* g = gw + (size_t)ra*2*D_;
        g_gv[gtid] = g[dd] + g[D_+dd];
    }
    int wid = gtid >> 5, lane = gtid & 31;
    if (wid < 4*D_){
        int ra = wid/D_, d = wid%D_;
        const float* krow = kw + ((size_t)ra*D_ + d)*D_;
        const float* s2   = sw + (size_t)ra*2*D_ + D_;
        float acc = 0.f;
        for (int e = lane; e < D_; e += 32) acc += krow[e]*s2[e];
        acc = warpsum(acc);
        if (!lane) g_kv[wid] = acc;
    }
}

// ---------------- one pass over x0 ----------------
__global__ void __launch_bounds__(256) k_xprep(const float* __restrict__ x0,
                                               const float* __restrict__ pos1,
                                               const float* __restrict__ pos2){
    int blk = blockIdx.x; int b = blk >> 2, ch = blk & 3;
    int tid = threadIdx.x;
    int wid = tid >> 5, lane = tid & 31;
    int base = b*L_ + ch*128;
    for (int r = wid; r < 128; r += 8){
        const float* xr = x0 + (size_t)(base+r)*D_;
        float a0=0.f, a1=0.f, a2=0.f, a3=0.f;
#pragma unroll
        for (int j = 0; j < 24; j++){
            int e = lane + j*32; float xv = xr[e];
            a0 += xv*g_gv[e];
            a1 += xv*g_kv[D_+e];
            a2 += xv*g_gv[2*D_+e];
            a3 += xv*g_kv[3*D_+e];
        }
        a0=warpsum(a0); a1=warpsum(a1); a2=warpsum(a2); a3=warpsum(a3);
        if (!lane){
            int row = base + r;
            g_R[row] = a0; g_R[BL+row] = a1; g_R[2*BL+row] = a2; g_R[3*BL+row] = a3;
        }
    }
    __shared__ float s1[128], s2[128];
    if (tid < 128){ s1[tid] = pos1[base+tid]; s2[tid] = pos2[base+tid]; }
    __syncthreads();
#pragma unroll
    for (int c0 = 0; c0 < 3; c0++){
        int col = tid + c0*256;
        const float* xb = x0 + (size_t)base*D_ + col;
        float e1 = 0.f, e2 = 0.f;
        for (int l = 0; l < 128; l++){
            float xv = xb[(size_t)l*D_];
            e1 += s1[l]*xv; e2 += s2[l]*xv;
        }
        g_bpart[((4+ch)*B_ + b)*D_ + col] = e1;
        g_bpart[((8+ch)*B_ + b)*D_ + col] = e2;
    }
    if (tid == 0){
        float t1 = 0.f, t2 = 0.f;
        for (int l = 0; l < 128; l++){ t1 += s1[l]; t2 += s2[l]; }
        atomicAdd(&g_sc[b], t1); atomicAdd(&g_sc[32+b], t2);
    }
}

// ---------------- per-c dots of p0 ----------------
__global__ void __launch_bounds__(256) k_pdots(){
    int w = (blockIdx.x*256 + threadIdx.x) >> 5;
    int lane = threadIdx.x & 31;
    if (w >= C_) return;
    const float* pr = g_p0 + (size_t)w*D_;
    float a0=0.f,a1=0.f,a2=0.f,a3=0.f;
#pragma unroll
    for (int j=0;j<24;j++){
        int e = lane + j*32; float pv = pr[e];
        a0 += pv*g_kv[e];
        a1 += pv*g_kv[2*D_+e];
        a2 += pv*g_gv[D_+e];
        a3 += pv*g_gv[3*D_+e];
    }
    a0=warpsum(a0);a1=warpsum(a1);a2=warpsum(a2);a3=warpsum(a3);
    if (!lane){ g_pd[w]=a0; g_pd[128+w]=a1; g_pd[256+w]=a2; g_pd[384+w]=a3; }
}

// ---------------- layer0 RA1 (batch-independent) ----------------
__global__ void __launch_bounds__(128) k_ra1_l0(){
    __shared__ float a[C_];
    int tid = threadIdx.x;
    if (tid < C_) a[tid] = g_pd[tid];
    __syncthreads();
    if (tid == 0){
        float m = -1e30f;
        for (int c=0;c<C_;c++) m = fmaxf(m, a[c]);
        float s = 0.f;
        for (int c=0;c<C_;c++){ a[c] = expf(a[c]-m); s += a[c]; }
        float inv = 1.f/s;
        for (int c=0;c<C_;c++) a[c] *= inv;
    }
    __syncthreads();
    int n = blockIdx.x*128 + tid;
    float acc = 0.f;
    for (int c=0;c<C_;c++) acc += a[c]*g_p0[(size_t)c*D_+n];
    g_u0[n] = acc;
}

// ---------------- GEMV: ctxA0 = u0@W + bias ----------------
__global__ void __launch_bounds__(128) k_gemv(const float* __restrict__ W,
                                              const float* __restrict__ bias){
    int n = blockIdx.x*128 + threadIdx.x;
    int kc = blockIdx.y;
    float acc = (kc==0) ? bias[n] : 0.f;
    const float* Wp = W + (size_t)kc*96*D_ + n;
    const float* u = g_u0 + kc*96;
#pragma unroll 4
    for (int k=0;k<96;k++) acc += u[k]*Wp[(size_t)k*D_];
    atomicAdd(&g_ctxA0[n], acc);
}

// ---------------- gates + masked softmax + scalar reductions ----------------
__global__ void __launch_bounds__(512) k_gates(int li, const int* __restrict__ mask,
                        const float* __restrict__ pos1, const float* __restrict__ pos2,
                        const float* __restrict__ gwp, const float* __restrict__ gbp){
    int b = blockIdx.x, tid = threadIdx.x;
    __shared__ float sh[16];
    __shared__ float sc[4];
    if (li == 0){
        float d0 = blockdot768(g_ctxA0, gwp, sh, 512);
        float d1 = blockdot768(g_ctxA0, g_kv + D_, sh, 512);
        if (tid == 0){ sc[0] = d0 + gbp[0]; sc[1] = d1; }
    } else {
        const float* cA1 = g_ctxA1 + (size_t)b*D_;
        float d0 = blockdot768(cA1, gwp, sh, 512);
        float d1 = blockdot768(g_ctxA0, g_gv + 2*D_, sh, 512);
        float d2 = blockdot768(g_ctxA0, g_kv + 3*D_, sh, 512);
        float d3 = blockdot768(cA1, g_kv + 3*D_, sh, 512);
        if (tid == 0){ sc[0]=d0+gbp[0]; sc[1]=d1; sc[2]=d2; sc[3]=d3; }
    }
    __syncthreads();
    int row = b*L_ + tid;
    float g, sk, g0v = 0.f;
    if (li == 0){
        g = sigm(g_R[row] + sc[0]);
        sk = 2.f*g_R[BL+row] + g*sc[1];
        g_g0[row] = g;
    } else {
        g0v = g_g0[row];
        g = sigm(2.f*g_R[2*BL+row] + g0v*sc[1] + sc[0]);
        sk = 4.f*g_R[3*BL+row] + 2.f*g0v*sc[2] + g*sc[3];
    }
    if (!mask[row]) sk = -1e30f;
    __shared__ float sm[16];
    __shared__ float bc;
    float m = warpmax(sk);
    if ((tid & 31) == 0) sm[tid>>5] = m;
    __syncthreads();
    if (tid == 0){
        float mm = sm[0];
        for (int i = 1; i < 16; i++) mm = fmaxf(mm, sm[i]);
        bc = mm;
    }
    __syncthreads();
    float e = expf(sk - bc);
    float ssum = warpsum(e);
    __syncthreads();
    if ((tid & 31) == 0) sm[tid>>5] = ssum;
    __syncthreads();
    if (tid == 0){
        float ss = 0.f;
        for (int i = 0; i < 16; i++) ss += sm[i];
        bc = ss;
    }
    __syncthreads();
    float a = e / bc;
    g_a2[row] = a;
    __shared__ float red[16][4];
    float r0, r1, r2, r3;
    if (li == 0){ r0 = a*g; r1 = pos1[row]*g; r2 = pos2[row]*g; r3 = 0.f; }
    else        { r0 = a*g0v; r1 = a*g; r2 = pos1[row]*g; r3 = pos2[row]*g; }
    r0=warpsum(r0); r1=warpsum(r1); r2=warpsum(r2); r3=warpsum(r3);
    if ((tid & 31) == 0){
        int w = tid>>5;
        red[w][0]=r0; red[w][1]=r1; red[w][2]=r2; red[w][3]=r3;
    }
    __syncthreads();
    if (tid == 0){
        float t0=0,t1=0,t2=0,t3=0;
        for (int i = 0; i < 16; i++){ t0+=red[i][0]; t1+=red[i][1]; t2+=red[i][2]; t3+=red[i][3]; }
        if (li == 0){ g_sc[64+b]=t0; g_sc[96+b]=t1; g_sc[128+b]=t2; }
        else        { g_sc[160+b]=t0; g_sc[192+b]=t1; g_sc[224+b]=t2; g_sc[256+b]=t3; }
    }
}

// ---------------- passB: a2 @ x0 partials ----------------
__global__ void __launch_bounds__(256) k_passB(const float* __restrict__ x0){
    int blk = blockIdx.x; int b = blk >> 2, ch = blk & 3;
    int tid = threadIdx.x;
    __shared__ float sa[128];
    if (tid < 128) sa[tid] = g_a2[b*L_ + ch*128 + tid];
    __syncthreads();
#pragma unroll
    for (int c0 = 0; c0 < 3; c0++){
        int col = tid + c0*256;
        const float* xb = x0 + ((size_t)b*L_ + ch*128)*D_ + col;
        float au = 0.f;
        for (int l = 0; l < 128; l++) au += sa[l]*xb[(size_t)l*D_];
        g_bpart[(ch*B_ + b)*D_ + col] = au;
    }
}

// ---------------- layer1 RA1 ----------------
__global__ void __launch_bounds__(256) k_ra1_l1(const float* __restrict__ gwp,
                                                const float* __restrict__ gbp){
    int b = blockIdx.x, tid = threadIdx.x;
    __shared__ float sh[8];
    __shared__ float sc2[2];
    __shared__ float a1[C_], g0p[C_];
    __shared__ float sag;
    const float* c20 = g_ctx2 + (size_t)b*D_;
    float d0 = blockdot768(c20, gwp, sh, 256);
    float d1 = blockdot768(c20, g_kv + 2*D_, sh, 256);
    if (tid == 0){ sc2[0] = d0 + gbp[0]; sc2[1] = d1; }
    __syncthreads();
    if (tid < C_){
        float gp = sigm(g_pd[256+tid] + sc2[0]);
        g0p[tid] = gp;
        a1[tid] = 2.f*g_pd[128+tid] + gp*sc2[1];
    }
    __syncthreads();
    if (tid == 0){
        float m = -1e30f;
        for (int c=0;c<C_;c++) m = fmaxf(m, a1[c]);
        float s = 0.f;
        for (int c=0;c<C_;c++){ a1[c] = expf(a1[c]-m); s += a1[c]; }
        float inv = 1.f/s, sg = 0.f;
        for (int c=0;c<C_;c++){ a1[c] *= inv; sg += a1[c]*g0p[c]; }
        sag = sg; g_sc[288+b] = sg;
    }
    __syncthreads();
    for (int n = tid; n < D_; n += 256){
        float s = 0.f;
        for (int c=0;c<C_;c++) s += a1[c]*g_p0[(size_t)c*D_+n];
        g_u1[b*D_+n] = 2.f*s + sag*c20[n];
    }
}

// ---------------- A-assembly ----------------
__device__ __forceinline__ float4 f4sum4(int grp, int m, int kg){
    float4 a = *(const float4*)(g_bpart + ((size_t)(grp+0)*B_+m)*D_ + kg);
    float4 b = *(const float4*)(g_bpart + ((size_t)(grp+1)*B_+m)*D_ + kg);
    float4 c = *(const float4*)(g_bpart + ((size_t)(grp+2)*B_+m)*D_ + kg);
    float4 d = *(const float4*)(g_bpart + ((size_t)(grp+3)*B_+m)*D_ + kg);
    return make_float4(a.x+b.x+c.x+d.x, a.y+b.y+c.y+d.y, a.z+b.z+c.z+d.z, a.w+b.w+c.w+d.w);
}
__device__ __forceinline__ float4 loadA4(const float* __restrict__ A, int amode,
                                         int m, int M, int kg, int K){
    if (m >= M) return make_float4(0.f,0.f,0.f,0.f);
    if (amode == 0) return *(const float4*)(A + (size_t)m*K + kg);
    if (amode == 1){
        float4 s = f4sum4(0, m, kg);
        float4 c = *(const float4*)(g_ctxA0 + kg);
        float sg = g_sc[64+m];
        return make_float4(2.f*s.x+sg*c.x, 2.f*s.y+sg*c.y, 2.f*s.z+sg*c.z, 2.f*s.w+sg*c.w);
    }
    if (amode == 2){
        float4 s = f4sum4(0, m, kg);
        float4 c0 = *(const float4*)(g_ctxA0 + kg);
        float4 c1 = *(const float4*)(g_ctxA1 + (size_t)m*D_ + kg);
        float sa = 2.f*g_sc[160+m], sb = g_sc[192+m];
        return make_float4(4.f*s.x+sa*c0.x+sb*c1.x, 4.f*s.y+sa*c0.y+sb*c1.y,
                           4.f*s.z+sa*c0.z+sb*c1.z, 4.f*s.w+sa*c0.w+sb*c1.w);
    }
    // amode 3: e12
    int grp = (kg < D_) ? 4 : 8;
    int k2 = (kg < D_) ? kg : kg - D_;
    float4 s = f4sum4(grp, m, k2);
    float4 c0 = *(const float4*)(g_ctxA0 + k2);
    float4 c1 = *(const float4*)(g_ctxA1 + (size_t)m*D_ + k2);
    float pg0 = 2.f*((kg < D_) ? g_sc[96+m] : g_sc[128+m]);
    float pg1 = (kg < D_) ? g_sc[224+m] : g_sc[256+m];
    float inv = 1.f/((kg < D_) ? g_sc[m] : g_sc[32+m]);
    return make_float4((4.f*s.x+pg0*c0.x+pg1*c1.x)*inv, (4.f*s.y+pg0*c0.y+pg1*c1.y)*inv,
                       (4.f*s.z+pg0*c0.z+pg1*c1.z)*inv, (4.f*s.w+pg0*c0.w+pg1*c1.w)*inv);
}

// ---------------- generic 128-row TF32 split-K GEMM ----------------
__global__ void __launch_bounds__(256) k_tcgemm(const float* __restrict__ A,
        const float* __restrict__ W, float* __restrict__ out,
        const float* __restrict__ bias, int M, int K, int KCH, int amode){
    __shared__ unsigned As[2][128][20];
    __shared__ unsigned Bs[2][16][132];
    int tid = threadIdx.x;
    int lane = tid & 31, g = lane >> 2, tg = lane & 3;
    int wid = tid >> 5, wm = wid >> 2, wn = wid & 3;
    int n0 = blockIdx.x * 128;
    int kb = blockIdx.y;
    int m0 = blockIdx.z * 128;
    int kbase = kb * KCH;
    int NS = KCH / 16;

    float cacc[4][4][4];
#pragma unroll
    for (int i = 0; i < 4; i++)
#pragma unroll
        for (int j = 0; j < 4; j++)
#pragma unroll
            for (int q = 0; q < 4; q++) cacc[i][j][q] = 0.f;

    int a_r = tid >> 2, a_c = (tid & 3) * 4;
    int b_r = tid >> 5, b_c = (tid & 31) * 4;

    float4 pa[2], pb[2];
#pragma unroll
    for (int r = 0; r < 2; r++){
        pa[r] = loadA4(A, amode, m0 + a_r + r*64, M, kbase + a_c, K);
        pb[r] = *(const float4*)(W + (size_t)(kbase + b_r + r*8)*D_ + n0 + b_c);
    }
#pragma unroll
    for (int r = 0; r < 2; r++){
        uint4 ua = { f2tf(pa[r].x), f2tf(pa[r].y), f2tf(pa[r].z), f2tf(pa[r].w) };
        *(uint4*)&As[0][a_r + r*64][a_c] = ua;
        uint4 ub = { f2tf(pb[r].x), f2tf(pb[r].y), f2tf(pb[r].z), f2tf(pb[r].w) };
        *(uint4*)&Bs[0][b_r + r*8][b_c] = ub;
    }
    __syncthreads();

    for (int s = 0; s < NS; s++){
        int cur = s & 1;
        if (s < NS-1){
            int kg = kbase + (s+1)*16;
#pragma unroll
            for (int r = 0; r < 2; r++){
                pa[r] = loadA4(A, amode, m0 + a_r + r*64, M, kg + a_c, K);
                pb[r] = *(const float4*)(W + (size_t)(kg + b_r + r*8)*D_ + n0 + b_c);
            }
        }
#pragma unroll
        for (int ks = 0; ks < 2; ks++){
            int k8 = ks*8;
            unsigned af[4][4], bf[4][2];
#pragma unroll
            for (int i = 0; i < 4; i++){
                int r = wm*64 + i*16 + g;
                af[i][0] = As[cur][r][k8+tg];
                af[i][1] = As[cur][r+8][k8+tg];
                af[i][2] = As[cur][r][k8+tg+4];
                af[i][3] = As[cur][r+8][k8+tg+4];
            }
#pragma unroll
            for (int j = 0; j < 4; j++){
                int c0 = wn*32 + j*8 + g;
                bf[j][0] = Bs[cur][k8+tg][c0];
                bf[j][1] = Bs[cur][k8+tg+4][c0];
            }
#pragma unroll
            for (int i = 0; i < 4; i++)
#pragma unroll
                for (int j = 0; j < 4; j++)
                    mma_tf32(cacc[i][j], af[i][0], af[i][1], af[i][2], af[i][3],
                             bf[j][0], bf[j][1]);
        }
        if (s < NS-1){
            int nxt = cur ^ 1;
#pragma unroll
            for (int r = 0; r < 2; r++){
                uint4 ua = { f2tf(pa[r].x), f2tf(pa[r].y), f2tf(pa[r].z), f2tf(pa[r].w) };
                *(uint4*)&As[nxt][a_r + r*64][a_c] = ua;
                uint4 ub = { f2tf(pb[r].x), f2tf(pb[r].y), f2tf(pb[r].z), f2tf(pb[r].w) };
                *(uint4*)&Bs[nxt][b_r + r*8][b_c] = ub;
            }
        }
        __syncthreads();
    }

#pragma unroll
    for (int i = 0; i < 4; i++){
#pragma unroll
        for (int half = 0; half < 2; half++){
            int m = m0 + wm*64 + i*16 + g + half*8;
            if (m < M){
#pragma unroll
                for (int j = 0; j < 4; j++){
                    int n = n0 + wn*32 + j*8 + 2*tg;
                    float v0 = cacc[i][j][half*2+0];
                    float v1 = cacc[i][j][half*2+1];
                    if (kb == 0 && bias){ v0 += bias[n]; v1 += bias[n+1]; }
                    atomicAdd(out + (size_t)m*D_ + n,     v0);
                    atomicAdd(out + (size_t)m*D_ + n + 1, v1);
                }
            }
        }
    }
}

// ---------------- dedicated M=32 TF32 split-K GEMM ----------------
__global__ void __launch_bounds__(256) k_tcgemm32(const float* __restrict__ A,
        const float* __restrict__ W, float* __restrict__ out,
        const float* __restrict__ bias, int K, int KCH, int amode){
    __shared__ unsigned As[2][32][20];
    __shared__ unsigned Bs[2][16][132];
    const int M = 32;
    int tid = threadIdx.x;
    int lane = tid & 31, g = lane >> 2, tg = lane & 3;
    int wid = tid >> 5, wm = wid >> 2, wn = wid & 3;
    int n0 = blockIdx.x * 128;
    int kb = blockIdx.y;
    int kbase = kb * KCH;
    int NS = KCH / 16;

    float cacc[4][4];
#pragma unroll
    for (int j = 0; j < 4; j++)
#pragma unroll
        for (int q = 0; q < 4; q++) cacc[j][q] = 0.f;

    int a_r = tid >> 2, a_c = (tid & 3) * 4;
    int b_r = tid >> 5, b_c = (tid & 31) * 4;

    float4 pa = make_float4(0.f,0.f,0.f,0.f), pb[2];
    if (tid < 128) pa = loadA4(A, amode, a_r, M, kbase + a_c, K);
#pragma unroll
    for (int r = 0; r < 2; r++)
        pb[r] = *(const float4*)(W + (size_t)(kbase + b_r + r*8)*D_ + n0 + b_c);
    if (tid < 128){
        uint4 ua = { f2tf(pa.x), f2tf(pa.y), f2tf(pa.z), f2tf(pa.w) };
        *(uint4*)&As[0][a_r][a_c] = ua;
    }
#pragma unroll
    for (int r = 0; r < 2; r++){
        uint4 ub = { f2tf(pb[r].x), f2tf(pb[r].y), f2tf(pb[r].z), f2tf(pb[r].w) };
        *(uint4*)&Bs[0][b_r + r*8][b_c] = ub;
    }
    __syncthreads();

    for (int s = 0; s < NS; s++){
        int cur = s & 1;
        if (s < NS-1){
            int kg = kbase + (s+1)*16;
            if (tid < 128) pa = loadA4(A, amode, a_r, M, kg + a_c, K);
#pragma unroll
            for (int r = 0; r < 2; r++)
                pb[r] = *(const float4*)(W + (size_t)(kg + b_r + r*8)*D_ + n0 + b_c);
        }
#pragma unroll
        for (int ks = 0; ks < 2; ks++){
            int k8 = ks*8;
            unsigned af[4], bf[4][2];
            int r = wm*16 + g;
            af[0] = As[cur][r][k8+tg];
            af[1] = As[cur][r+8][k8+tg];
            af[2] = As[cur][r][k8+tg+4];
            af[3] = As[cur][r+8][k8+tg+4];
#pragma unroll
            for (int j = 0; j < 4; j++){
                int c0 = wn*32 + j*8 + g;
                bf[j][0] = Bs[cur][k8+tg][c0];
                bf[j][1] = Bs[cur][k8+tg+4][c0];
            }
#pragma unroll
            for (int j = 0; j < 4; j++)
                mma_tf32(cacc[j], af[0], af[1], af[2], af[3], bf[j][0], bf[j][1]);
        }
        if (s < NS-1){
            int nxt = cur ^ 1;
            if (tid < 128){
                uint4 ua = { f2tf(pa.x), f2tf(pa.y), f2tf(pa.z), f2tf(pa.w) };
                *(uint4*)&As[nxt][a_r][a_c] = ua;
            }
#pragma unroll
            for (int r = 0; r < 2; r++){
                uint4 ub = { f2tf(pb[r].x), f2tf(pb[r].y), f2tf(pb[r].z), f2tf(pb[r].w) };
                *(uint4*)&Bs[nxt][b_r + r*8][b_c] = ub;
            }
        }
        __syncthreads();
    }

#pragma unroll
    for (int half = 0; half < 2; half++){
        int m = wm*16 + g + half*8;
#pragma unroll
        for (int j = 0; j < 4; j++){
            int n = n0 + wn*32 + j*8 + 2*tg;
            float v0 = cacc[j][half*2+0];
            float v1 = cacc[j][half*2+1];
            if (kb == 0 && bias){ v0 += bias[n]; v1 += bias[n+1]; }
            atomicAdd(out + (size_t)m*D_ + n,     v0);
            atomicAdd(out + (size_t)m*D_ + n + 1, v1);
        }
    }
}

// ---------------- final: tanh recombination + logits + argmax ----------------
__global__ void __launch_bounds__(256) k_tanh(const float* __restrict__ gw,
        const float* __restrict__ gb, const float* __restrict__ fc2w,
        const float* __restrict__ fc2b, float* __restrict__ out,
        int wlog, int predoff){
    int b = blockIdx.x, tid = threadIdx.x, lane = tid & 31, wid = tid >> 5;
    __shared__ float sh[8];
    __shared__ float cw0[D_], cw1[D_], t1s[D_], w2[D_];
    __shared__ float sc3[3];
    __shared__ float lg[C_];
    const float* c20 = g_ctx2 + (size_t)b*D_;
    const float* c21 = g_ctx2 + (size_t)(B_+b)*D_;
    for (int e = tid; e < D_; e += 256){
        cw0[e] = g_pcw[(size_t)(97+b)*D_+e];
        cw1[e] = g_pcw[(size_t)(129+b)*D_+e];
        t1s[e] = g_t1[b*D_+e];
        w2[e]  = fc2w[e];
    }
    float d0 = blockdot768(c20, gw + 1*2*D_, sh, 256);
    float d1 = blockdot768(c20, g_gv + 3*D_, sh, 256);
    float d2 = blockdot768(c21, gw + 3*2*D_, sh, 256);
    if (tid == 0){ sc3[0] = d0 + gb[1]; sc3[1] = d1; sc3[2] = d2 + gb[3]; }
    __syncthreads();
    for (int c = wid; c < C_; c += 8){
        float gp0 = sigm(g_pd[256+c] + sc3[0]);
        float gp1 = sigm(2.f*g_pd[384+c] + gp0*sc3[1] + sc3[2]);
        const float* pw = g_pcw + (size_t)c*D_;
        float acc = 0.f;
#pragma unroll
        for (int j = 0; j < 24; j++){
            int n = lane + j*32;
            float z = 4.f*pw[n] + 2.f*gp0*cw0[n] + gp1*cw1[n] + t1s[n];
            acc += tanhf(z)*w2[n];
        }
        acc = warpsum(acc);
        if (!lane){
            float l = sigm(acc + fc2b[0]);
            lg[c] = l;
            if (wlog) out[b*C_+c] = l;
        }
    }
    __syncthreads();
    if (tid == 0 && predoff >= 0){
        float best = lg[0]; int bi = 0;
        for (int c = 1; c < C_; c++)
            if (lg[c] > best){ best = lg[c]; bi = c; }
        out[predoff + b] = (float)bi;
    }
}

// ---------------- streams, created+warmed at load time ----------------
namespace {
struct GStreams {
    cudaStream_t s1 = 0, s2 = 0;
    cudaEvent_t ev0, evA, evP, evB, evC0, evC, evT, evQ, evW;
    bool ok = false;
    GStreams(){
        bool o = true;
        o = o && cudaStreamCreateWithFlags(&s1, cudaStreamNonBlocking) == cudaSuccess;
        o = o && cudaStreamCreateWithFlags(&s2, cudaStreamNonBlocking) == cudaSuccess;
        o = o && cudaEventCreateWithFlags(&ev0,  cudaEventDisableTiming) == cudaSuccess;
        o = o && cudaEventCreateWithFlags(&evA,  cudaEventDisableTiming) == cudaSuccess;
        o = o && cudaEventCreateWithFlags(&evP,  cudaEventDisableTiming) == cudaSuccess;
        o = o && cudaEventCreateWithFlags(&evB,  cudaEventDisableTiming) == cudaSuccess;
        o = o && cudaEventCreateWithFlags(&evC0, cudaEventDisableTiming) == cudaSuccess;
        o = o && cudaEventCreateWithFlags(&evC,  cudaEventDisableTiming) == cudaSuccess;
        o = o && cudaEventCreateWithFlags(&evT,  cudaEventDisableTiming) == cudaSuccess;
        o = o && cudaEventCreateWithFlags(&evQ,  cudaEventDisableTiming) == cudaSuccess;
        o = o && cudaEventCreateWithFlags(&evW,  cudaEventDisableTiming) == cudaSuccess;
        if (o){
            k_zp0<<<291,256,0,s1>>>();
            k_zp0<<<291,256,0,s2>>>();
            o = o && cudaStreamSynchronize(s1) == cudaSuccess;
            o = o && cudaStreamSynchronize(s2) == cudaSuccess;
        }
        ok = o;
    }
};
GStreams gs;
}

// ---------------- host orchestration ----------------
extern "C" void kernel_launch(void* const* d_in, const int* in_sizes, int n_in,
                              void* d_out, int out_size){
    (void)in_sizes; (void)n_in;
    const float* x_in  = (const float*)d_in[0];
    const float* pos1  = (const float*)d_in[1];
    const float* pos2  = (const float*)d_in[2];
    const int*   mask  = (const int*)  d_in[3];
    const float* emb   = (const float*)d_in[4];
    const float* rel_w = (const float*)d_in[5];
    const float* rel_b = (const float*)d_in[6];
    const float* kw    = (const float*)d_in[9];
    const float* vw    = (const float*)d_in[11];
    const float* vb    = (const float*)d_in[12];
    const float* sw    = (const float*)d_in[13];
    const float* gw    = (const float*)d_in[15];
    const float* gb    = (const float*)d_in[16];
    const float* fc1w  = (const float*)d_in[17];
    const float* fc1b  = (const float*)d_in[18];
    const float* fc2w  = (const float*)d_in[19];
    const float* fc2b  = (const float*)d_in[20];
    float* out = (float*)d_out;

    float *p_p0, *p_u1, *p_ctxA1, *p_ctx2, *p_t1, *p_pcw;
    cudaGetSymbolAddress((void**)&p_p0,    g_p0);
    cudaGetSymbolAddress((void**)&p_u1,    g_u1);
    cudaGetSymbolAddress((void**)&p_ctxA1, g_ctxA1);
    cudaGetSymbolAddress((void**)&p_ctx2,  g_ctx2);
    cudaGetSymbolAddress((void**)&p_t1,    g_t1);
    cudaGetSymbolAddress((void**)&p_pcw,   g_pcw);

    bool mk = gs.ok;
    cudaStream_t S0 = 0;
    cudaStream_t S1 = mk ? gs.s1 : (cudaStream_t)0;
    cudaStream_t S2 = mk ? gs.s2 : (cudaStream_t)0;
#define REC(ev, s)   do{ if (mk) cudaEventRecord(ev, s); }while(0)
#define WAITE(s, ev) do{ if (mk) cudaStreamWaitEvent(s, ev, 0); }while(0)

    // legal fork point: event recorded on origin stream BEFORE any branch work
    REC(gs.ev0, S0);

    // stream 0: zero+prep (kv/gv + all atomic-output zeros except p0)
    k_prepzero<<<483,256,0,S0>>>(kw, sw, gw);
    REC(gs.evA, S0);

    // branch S1 (forked via ev0): p0 = emb@rel_w + rel_b
    WAITE(S1, gs.ev0);
    k_zp0<<<291,256,0,S1>>>();
    k_tcgemm<<<dim3(6,8,1),256,0,S1>>>(emb, rel_w, p_p0, rel_b, 97, 768, 96, 0);
    REC(gs.evP, S1);

    // branch S2: PCW rows 0-96 = p0 @ fc1w  (needs p0 [evP] and pcw zeros [evA])
    WAITE(S2, gs.evA);
    WAITE(S2, gs.evP);
    k_tcgemm<<<dim3(6,8,1),256,0,S2>>>(p_p0, fc1w, p_pcw, nullptr, 97, 768, 96, 0);
    REC(gs.evQ, S2);

    // S1 continues: pdots -> ra1_l0 -> gemv (needs kv/gv from evA)
    WAITE(S1, gs.evA);
    k_pdots<<<13,256,0,S1>>>();
    k_ra1_l0<<<6,128,0,S1>>>();
    k_gemv<<<dim3(6,8),128,0,S1>>>(vw, vb);
    REC(gs.evB, S1);

    // stream 0: the big x0 pass (overlaps with S1/S2)
    k_xprep<<<128,256,0,S0>>>(x_in, pos1, pos2);

    // join, then the serial core
    WAITE(S0, gs.evB);
    k_gates<<<B_,512,0,S0>>>(0, mask, pos1, pos2, gw, gb);
    k_passB<<<128,256,0,S0>>>(x_in);
    k_tcgemm32<<<dim3(6,8),256,0,S0>>>(nullptr, vw + (size_t)1*D_*D_, p_ctx2, vb + 1*D_, 768, 96, 1);
    REC(gs.evC0, S0);

    // branch S2: PCW rows 97-128 = ctx2_0 @ fc1w
    WAITE(S2, gs.evC0);
    k_tcgemm32<<<dim3(6,8),256,0,S2>>>(p_ctx2, fc1w, p_pcw + (size_t)97*D_, nullptr, 768, 96, 0);
    REC(gs.evW, S2);

    k_ra1_l1<<<B_,256,0,S0>>>(gw + (size_t)1*2*D_, gb + 1);
    k_tcgemm32<<<dim3(6,8),256,0,S0>>>(p_u1, vw + (size_t)2*D_*D_, p_ctxA1, vb + 2*D_, 768, 96, 0);
    k_gates<<<B_,512,0,S0>>>(1, mask, pos1, pos2, gw + (size_t)2*2*D_, gb + 2);
    REC(gs.evC, S0);

    // branch S1: t1 = [e1|e2] @ fc1w[768:2304] + fc1b
    WAITE(S1, gs.evC);
    k_tcgemm32<<<dim3(6,8),256,0,S1>>>(nullptr, fc1w + (size_t)768*768, p_t1, fc1b, 1536, 192, 3);
    REC(gs.evT, S1);

    k_passB<<<128,256,0,S0>>>(x_in);
    k_tcgemm32<<<dim3(6,8),256,0,S0>>>(nullptr, vw + (size_t)3*D_*D_, p_ctx2 + (size_t)B_*D_, vb + 3*D_, 768, 96, 2);
    k_tcgemm32<<<dim3(6,8),256,0,S0>>>(p_ctx2 + (size_t)B_*D_, fc1w, p_pcw + (size_t)129*D_, nullptr, 768, 96, 0);

    WAITE(S0, gs.evT);
    WAITE(S0, gs.evQ);
    WAITE(S0, gs.evW);
    int wlog = (out_size >= GM) ? 1 : 0;
    int predoff = -1;
    if (out_size >= GM + B_) predoff = GM;
    else if (out_size == B_){ predoff = 0; wlog = 0; }
    k_tanh<<<B_,256,0,S0>>>(gw, gb, fc2w, fc2b, out, wlog, predoff);
#undef REC
#undef WAITE
}